// round 1
// baseline (speedup 1.0000x reference)
#include <cuda_runtime.h>
#include <math.h>
#include <stdint.h>

// ---------------- problem constants (fixed by the dataset) ----------------
#define N_M   8192
#define N_D   6144
#define NTOT  14336            // N_M + N_D
#define E_MM  131072
#define E_DD  98304
#define E_G   229376
#define EG_TOT (E_G + NTOT)    // real edges + self loops = 243712
#define HID   128
#define TPB   256

// ---------------- scratch (static device globals; no runtime alloc) -------
__device__ float g_ew_m[E_MM],  g_norm_m[E_MM];
__device__ float g_ew_d[E_DD],  g_norm_d[E_DD];
__device__ float g_deg_m[N_M],  g_dinv_m[N_M];
__device__ float g_deg_d[N_D],  g_dinv_d[N_D];
__device__ int   g_cnt_m[N_M],  g_row_m[N_M + 1],  g_cur_m[N_M];
__device__ int   g_eid_m[E_MM];
__device__ int   g_cnt_d[N_D],  g_row_d[N_D + 1],  g_cur_d[N_D];
__device__ int   g_eid_d[E_DD];
__device__ int   g_cnt_g[NTOT], g_row_g[NTOT + 1], g_cur_g[NTOT];
__device__ int   g_eid_g[EG_TOT];
__device__ float g_logits[(size_t)EG_TOT * 4];
__device__ float g_bufA[(size_t)NTOT * 256];
__device__ float g_bufB[(size_t)NTOT * 256];
__device__ float g_tmp [(size_t)NTOT * 128];
__device__ float g_xjk [(size_t)NTOT * 224];

// ---------------- small helpers ----------------
__device__ __forceinline__ float4 ld4(const float* p) { return *(const float4*)p; }

// ---------------- init ----------------
__global__ void k_init() {
    int i = blockIdx.x * blockDim.x + threadIdx.x;
    if (i < N_M)  { g_deg_m[i] = 1.0f; g_cnt_m[i] = 0; }   // self-loop weight 1
    if (i < N_D)  { g_deg_d[i] = 1.0f; g_cnt_d[i] = 0; }
    if (i < NTOT) { g_cnt_g[i] = 1; }                       // self loop counted in CSR
}

// ---------------- GCN prep: edge-weight gather + degree + count ----------
__global__ void k_gcn_prep(const int* __restrict__ edges, const float* __restrict__ mat,
                           int matN, float* __restrict__ ew, float* __restrict__ deg,
                           int* __restrict__ cnt, int E) {
    int e = blockIdx.x * blockDim.x + threadIdx.x;
    if (e >= E) return;
    int s = edges[e], d = edges[E + e];
    float w = mat[(size_t)s * matN + d];
    ew[e] = w;
    atomicAdd(&deg[d], w);
    atomicAdd(&cnt[d], 1);
}

__global__ void k_dinv(const float* __restrict__ deg, float* __restrict__ dinv, int n) {
    int i = blockIdx.x * blockDim.x + threadIdx.x;
    if (i < n) dinv[i] = rsqrtf(deg[i]);   // deg >= 1 always (self loop)
}

__global__ void k_norm(const int* __restrict__ edges, const float* __restrict__ ew,
                       const float* __restrict__ dinv, float* __restrict__ nrm, int E) {
    int e = blockIdx.x * blockDim.x + threadIdx.x;
    if (e >= E) return;
    nrm[e] = dinv[edges[e]] * ew[e] * dinv[edges[E + e]];
}

// ---------------- CSR build ----------------
// exclusive scan (single block, 1024 threads); also seeds the fill cursors.
__global__ void k_scan(const int* __restrict__ cnt, int* __restrict__ row,
                       int* __restrict__ cur, int n) {
    __shared__ int sh[1024];
    int t = threadIdx.x;
    int chunk = (n + 1023) / 1024;
    int lo = t * chunk, hi = min(lo + chunk, n);
    int sum = 0;
    for (int i = lo; i < hi; i++) sum += cnt[i];
    sh[t] = sum;
    __syncthreads();
    for (int off = 1; off < 1024; off <<= 1) {
        int v = 0;
        if (t >= off) v = sh[t - off];
        __syncthreads();
        if (t >= off) sh[t] += v;
        __syncthreads();
    }
    int run = (t == 0) ? 0 : sh[t - 1];
    for (int i = lo; i < hi; i++) { row[i] = run; cur[i] = run; run += cnt[i]; }
    if (t == 1023) row[n] = sh[1023];
}

__global__ void k_fill(const int* __restrict__ edges, int* __restrict__ cur,
                       int* __restrict__ eid, int E) {
    int e = blockIdx.x * blockDim.x + threadIdx.x;
    if (e >= E) return;
    int d = edges[E + e];
    int p = atomicAdd(&cur[d], 1);
    eid[p] = e;
}

__global__ void k_gcount(const int* __restrict__ edges) {
    int e = blockIdx.x * blockDim.x + threadIdx.x;
    if (e >= E_G) return;
    atomicAdd(&g_cnt_g[edges[E_G + e]], 1);
}

__global__ void k_gfill(const int* __restrict__ edges) {
    int e = blockIdx.x * blockDim.x + threadIdx.x;
    if (e >= E_G) return;
    int d = edges[E_G + e];
    int p = atomicAdd(&g_cur_g[d], 1);
    g_eid_g[p] = e;
}

__global__ void k_gfill_self() {
    int i = blockIdx.x * blockDim.x + threadIdx.x;
    if (i >= NTOT) return;
    int p = atomicAdd(&g_cur_g[i], 1);
    g_eid_g[p] = E_G + i;
}

// ---------------- f32 GEMM: C[M,Nc] = A[M,K] @ W[K,Nc] (+bias) ------------
// BM=BN=64, BK=32, 256 threads, 4x4 per thread. All dims divide tiles exactly.
__global__ void k_gemm(const float* __restrict__ A, int lda,
                       const float* __restrict__ W, int ldw,
                       const float* __restrict__ bias,
                       float* __restrict__ C, int ldc,
                       int M, int K, int Nc) {
    __shared__ float As[32][68];   // [k][m], padded to keep 16B alignment
    __shared__ float Ws[32][64];   // [k][n]
    int tid = threadIdx.x;
    int tx = tid & 15, ty = tid >> 4;
    int row0 = blockIdx.y * 64, col0 = blockIdx.x * 64;
    float acc[4][4] = {};
    for (int k0 = 0; k0 < K; k0 += 32) {
        // A tile 64x32 (512 float4)
        #pragma unroll
        for (int i = tid; i < 512; i += 256) {
            int r = i >> 3, c4 = i & 7;
            float4 v = ld4(A + (size_t)(row0 + r) * lda + k0 + c4 * 4);
            As[c4 * 4 + 0][r] = v.x; As[c4 * 4 + 1][r] = v.y;
            As[c4 * 4 + 2][r] = v.z; As[c4 * 4 + 3][r] = v.w;
        }
        // W tile 32x64 (512 float4)
        #pragma unroll
        for (int i = tid; i < 512; i += 256) {
            int r = i >> 4, c4 = i & 15;
            *(float4*)&Ws[r][c4 * 4] = ld4(W + (size_t)(k0 + r) * ldw + col0 + c4 * 4);
        }
        __syncthreads();
        #pragma unroll
        for (int k = 0; k < 32; k++) {
            float4 a = *(float4*)&As[k][ty * 4];
            float4 b = *(float4*)&Ws[k][tx * 4];
            acc[0][0] += a.x * b.x; acc[0][1] += a.x * b.y; acc[0][2] += a.x * b.z; acc[0][3] += a.x * b.w;
            acc[1][0] += a.y * b.x; acc[1][1] += a.y * b.y; acc[1][2] += a.y * b.z; acc[1][3] += a.y * b.w;
            acc[2][0] += a.z * b.x; acc[2][1] += a.z * b.y; acc[2][2] += a.z * b.z; acc[2][3] += a.z * b.w;
            acc[3][0] += a.w * b.x; acc[3][1] += a.w * b.y; acc[3][2] += a.w * b.z; acc[3][3] += a.w * b.w;
        }
        __syncthreads();
    }
    float4 bb = make_float4(0.f, 0.f, 0.f, 0.f);
    if (bias) bb = ld4(bias + col0 + tx * 4);
    #pragma unroll
    for (int i = 0; i < 4; i++) {
        float4 o = make_float4(acc[i][0] + bb.x, acc[i][1] + bb.y,
                               acc[i][2] + bb.z, acc[i][3] + bb.w);
        *(float4*)(C + (size_t)(row0 + ty * 4 + i) * ldc + col0 + tx * 4) = o;
    }
}

// ---------------- GCN aggregate (warp per dst node, 128 channels) ---------
__global__ void k_gcn_agg(const float* __restrict__ h, const int* __restrict__ edges,
                          const float* __restrict__ nrm, const float* __restrict__ dinv,
                          const int* __restrict__ row, const int* __restrict__ eid,
                          const float* __restrict__ bias,
                          float* __restrict__ out, int ldout, int n, int E, int relu) {
    int w = (blockIdx.x * blockDim.x + threadIdx.x) >> 5;
    int lane = threadIdx.x & 31;
    if (w >= n) return;
    int rs = row[w], re = row[w + 1];
    float4 acc = make_float4(0.f, 0.f, 0.f, 0.f);
    for (int j = rs; j < re; j++) {
        int e = eid[j];
        float nm = nrm[e];
        int s = edges[e];
        float4 v = ld4(h + (size_t)s * HID + lane * 4);
        acc.x += nm * v.x; acc.y += nm * v.y; acc.z += nm * v.z; acc.w += nm * v.w;
    }
    float di = dinv[w];
    float sw = di * di;
    float4 v = ld4(h + (size_t)w * HID + lane * 4);
    acc.x += sw * v.x; acc.y += sw * v.y; acc.z += sw * v.z; acc.w += sw * v.w;
    float4 b = ld4(bias + lane * 4);
    acc.x += b.x; acc.y += b.y; acc.z += b.z; acc.w += b.w;
    if (relu) {
        acc.x = fmaxf(acc.x, 0.f); acc.y = fmaxf(acc.y, 0.f);
        acc.z = fmaxf(acc.z, 0.f); acc.w = fmaxf(acc.w, 0.f);
    }
    *(float4*)(out + (size_t)w * ldout + lane * 4) = acc;
}

// ---------------- GATv2 edge logits (warp per edge) -----------------------
// HC = H*C (256 layer1, 128 layer2). Lane owns HC/32 contiguous channels;
// each 8-lane group covers exactly one head.
template <int HC>
__global__ void k_gat_logits(const float* __restrict__ xl, const float* __restrict__ xr,
                             const float* __restrict__ att, const int* __restrict__ edges) {
    int w = (blockIdx.x * blockDim.x + threadIdx.x) >> 5;
    int lane = threadIdx.x & 31;
    if (w >= EG_TOT) return;
    int s, d;
    if (w < E_G) { s = edges[w]; d = edges[E_G + w]; }
    else         { s = d = w - E_G; }
    const int CH = HC / 32;
    const float* pl = xl + (size_t)s * HC + lane * CH;
    const float* pr = xr + (size_t)d * HC + lane * CH;
    const float* pa = att + lane * CH;
    float p = 0.f;
    #pragma unroll
    for (int j = 0; j < CH; j += 4) {
        float4 a = ld4(pl + j), b = ld4(pr + j), c = ld4(pa + j);
        float t;
        t = a.x + b.x; t = t > 0.f ? t : 0.2f * t; p += t * c.x;
        t = a.y + b.y; t = t > 0.f ? t : 0.2f * t; p += t * c.y;
        t = a.z + b.z; t = t > 0.f ? t : 0.2f * t; p += t * c.z;
        t = a.w + b.w; t = t > 0.f ? t : 0.2f * t; p += t * c.w;
    }
    p += __shfl_xor_sync(0xffffffffu, p, 1);
    p += __shfl_xor_sync(0xffffffffu, p, 2);
    p += __shfl_xor_sync(0xffffffffu, p, 4);
    if ((lane & 7) == 0) g_logits[(size_t)w * 4 + (lane >> 3)] = p;
}

// ---------------- GATv2 node aggregate (warp per dst node) ----------------
// Local softmax over the node's incoming edges (CSR incl. self loop):
// pass1 = per-head max, pass2 = exp + weighted accumulate, then head-mean.
template <int HC>
__global__ void k_gat_node(const float* __restrict__ xl, const int* __restrict__ edges,
                           const float* __restrict__ bias,
                           float* __restrict__ out, int ldout, int elu) {
    int i = (blockIdx.x * blockDim.x + threadIdx.x) >> 5;
    int lane = threadIdx.x & 31;
    if (i >= NTOT) return;
    int rs = g_row_g[i], re = g_row_g[i + 1];

    // pass 1: per-head max (lane-parallel over edges)
    float4 mx = make_float4(-1e30f, -1e30f, -1e30f, -1e30f);
    for (int j = rs + lane; j < re; j += 32) {
        int e = g_eid_g[j];
        float4 lg = ld4(g_logits + (size_t)e * 4);
        mx.x = fmaxf(mx.x, lg.x); mx.y = fmaxf(mx.y, lg.y);
        mx.z = fmaxf(mx.z, lg.z); mx.w = fmaxf(mx.w, lg.w);
    }
    #pragma unroll
    for (int off = 16; off > 0; off >>= 1) {
        mx.x = fmaxf(mx.x, __shfl_xor_sync(0xffffffffu, mx.x, off));
        mx.y = fmaxf(mx.y, __shfl_xor_sync(0xffffffffu, mx.y, off));
        mx.z = fmaxf(mx.z, __shfl_xor_sync(0xffffffffu, mx.z, off));
        mx.w = fmaxf(mx.w, __shfl_xor_sync(0xffffffffu, mx.w, off));
    }

    // pass 2: exp + accumulate numerator (channel-parallel) and denominator
    const int CH = HC / 32;
    float num[CH];
    #pragma unroll
    for (int k = 0; k < CH; k++) num[k] = 0.f;
    float4 den = make_float4(0.f, 0.f, 0.f, 0.f);
    int hsel = lane >> 3;   // this lane's head
    for (int j = rs; j < re; j++) {
        int e = g_eid_g[j];
        int s = (e < E_G) ? edges[e] : (e - E_G);
        float4 lg = ld4(g_logits + (size_t)e * 4);
        float4 ex = make_float4(expf(lg.x - mx.x), expf(lg.y - mx.y),
                                expf(lg.z - mx.z), expf(lg.w - mx.w));
        den.x += ex.x; den.y += ex.y; den.z += ex.z; den.w += ex.w;
        float exh = (hsel == 0) ? ex.x : (hsel == 1) ? ex.y : (hsel == 2) ? ex.z : ex.w;
        const float* px = xl + (size_t)s * HC + lane * CH;
        #pragma unroll
        for (int k = 0; k < CH; k += 4) {
            float4 v = ld4(px + k);
            num[k] += exh * v.x; num[k + 1] += exh * v.y;
            num[k + 2] += exh * v.z; num[k + 3] += exh * v.w;
        }
    }
    float dh = (hsel == 0) ? den.x : (hsel == 1) ? den.y : (hsel == 2) ? den.z : den.w;
    float inv = 0.25f / dh;   // includes head-mean

    // head-mean: sum across lanes {l, l^8, l^16, l^24} (same channels, 4 heads)
    #pragma unroll
    for (int k = 0; k < CH; k++) {
        float v = num[k] * inv;
        v += __shfl_xor_sync(0xffffffffu, v, 8);
        v += __shfl_xor_sync(0xffffffffu, v, 16);
        num[k] = v;
    }
    if (lane < 8) {
        float o[CH];
        #pragma unroll
        for (int k = 0; k < CH; k++) {
            float v = num[k] + bias[lane * CH + k];
            if (elu) v = v > 0.f ? v : expm1f(v);
            o[k] = v;
        }
        float* po = out + (size_t)i * ldout + lane * CH;
        #pragma unroll
        for (int k = 0; k < CH; k += 4)
            *(float4*)(po + k) = make_float4(o[k], o[k + 1], o[k + 2], o[k + 3]);
    }
}

// ---------------- host orchestration ----------------
static inline void gemm(const float* A, int lda, const float* W, int ldw,
                        const float* bias, float* C, int ldc, int M, int K, int Nc) {
    dim3 grid(Nc / 64, M / 64);
    k_gemm<<<grid, 256>>>(A, lda, W, ldw, bias, C, ldc, M, K, Nc);
}

extern "C" void kernel_launch(void* const* d_in, const int* in_sizes, int n_in,
                              void* d_out, int out_size) {
    const float* mm_f = (const float*)d_in[0];
    const float* d_s  = (const float*)d_in[1];
    const float* msM  = (const float*)d_in[2];
    const float* dsM  = (const float*)d_in[3];
    const int*   e_mm = (const int*)d_in[4];
    const int*   e_dd = (const int*)d_in[5];
    const int*   e_g  = (const int*)d_in[6];
    const float* W_m1 = (const float*)d_in[7];  const float* b_m1 = (const float*)d_in[8];
    const float* W_m2 = (const float*)d_in[9];  const float* b_m2 = (const float*)d_in[10];
    const float* W_d1 = (const float*)d_in[11]; const float* b_d1 = (const float*)d_in[12];
    const float* W_d2 = (const float*)d_in[13]; const float* b_d2 = (const float*)d_in[14];
    const float* Wl1  = (const float*)d_in[15]; const float* Wr1  = (const float*)d_in[16];
    const float* att1 = (const float*)d_in[17]; const float* bias1 = (const float*)d_in[18];
    const float* Wl2  = (const float*)d_in[19]; const float* Wr2  = (const float*)d_in[20];
    const float* att2 = (const float*)d_in[21]; const float* bias2 = (const float*)d_in[22];
    const float* Wjk  = (const float*)d_in[23]; const float* bjk  = (const float*)d_in[24];
    float* out = (float*)d_out;

    // resolve device-global addresses (query only; capture-safe)
    float *p_ew_m, *p_norm_m, *p_ew_d, *p_norm_d;
    float *p_deg_m, *p_dinv_m, *p_deg_d, *p_dinv_d;
    int *p_cnt_m, *p_row_m, *p_cur_m, *p_eid_m;
    int *p_cnt_d, *p_row_d, *p_cur_d, *p_eid_d;
    int *p_cnt_g, *p_row_g, *p_cur_g;
    float *p_A, *p_B, *p_tmp, *p_xjk;
    cudaGetSymbolAddress((void**)&p_ew_m,  g_ew_m);   cudaGetSymbolAddress((void**)&p_norm_m, g_norm_m);
    cudaGetSymbolAddress((void**)&p_ew_d,  g_ew_d);   cudaGetSymbolAddress((void**)&p_norm_d, g_norm_d);
    cudaGetSymbolAddress((void**)&p_deg_m, g_deg_m);  cudaGetSymbolAddress((void**)&p_dinv_m, g_dinv_m);
    cudaGetSymbolAddress((void**)&p_deg_d, g_deg_d);  cudaGetSymbolAddress((void**)&p_dinv_d, g_dinv_d);
    cudaGetSymbolAddress((void**)&p_cnt_m, g_cnt_m);  cudaGetSymbolAddress((void**)&p_row_m,  g_row_m);
    cudaGetSymbolAddress((void**)&p_cur_m, g_cur_m);  cudaGetSymbolAddress((void**)&p_eid_m,  g_eid_m);
    cudaGetSymbolAddress((void**)&p_cnt_d, g_cnt_d);  cudaGetSymbolAddress((void**)&p_row_d,  g_row_d);
    cudaGetSymbolAddress((void**)&p_cur_d, g_cur_d);  cudaGetSymbolAddress((void**)&p_eid_d,  g_eid_d);
    cudaGetSymbolAddress((void**)&p_cnt_g, g_cnt_g);  cudaGetSymbolAddress((void**)&p_row_g,  g_row_g);
    cudaGetSymbolAddress((void**)&p_cur_g, g_cur_g);
    cudaGetSymbolAddress((void**)&p_A,   g_bufA);     cudaGetSymbolAddress((void**)&p_B,   g_bufB);
    cudaGetSymbolAddress((void**)&p_tmp, g_tmp);      cudaGetSymbolAddress((void**)&p_xjk, g_xjk);

    const int GB = TPB;
    auto blk = [](int n) { return (n + TPB - 1) / TPB; };
    auto wblk = [](int nwarps) { return (nwarps * 32 + TPB - 1) / TPB; };

    // ---- CSR / normalization prep ----
    k_init<<<blk(NTOT), GB>>>();
    k_gcn_prep<<<blk(E_MM), GB>>>(e_mm, msM, N_M, p_ew_m, p_deg_m, p_cnt_m, E_MM);
    k_gcn_prep<<<blk(E_DD), GB>>>(e_dd, dsM, N_D, p_ew_d, p_deg_d, p_cnt_d, E_DD);
    k_gcount<<<blk(E_G), GB>>>(e_g);
    k_dinv<<<blk(N_M), GB>>>(p_deg_m, p_dinv_m, N_M);
    k_dinv<<<blk(N_D), GB>>>(p_deg_d, p_dinv_d, N_D);
    k_norm<<<blk(E_MM), GB>>>(e_mm, p_ew_m, p_dinv_m, p_norm_m, E_MM);
    k_norm<<<blk(E_DD), GB>>>(e_dd, p_ew_d, p_dinv_d, p_norm_d, E_DD);
    k_scan<<<1, 1024>>>(p_cnt_m, p_row_m, p_cur_m, N_M);
    k_scan<<<1, 1024>>>(p_cnt_d, p_row_d, p_cur_d, N_D);
    k_scan<<<1, 1024>>>(p_cnt_g, p_row_g, p_cur_g, NTOT);
    k_fill<<<blk(E_MM), GB>>>(e_mm, p_cur_m, p_eid_m, E_MM);
    k_fill<<<blk(E_DD), GB>>>(e_dd, p_cur_d, p_eid_d, E_DD);
    k_gfill<<<blk(E_G), GB>>>(e_g);
    k_gfill_self<<<blk(NTOT), GB>>>();

    // ---- GCN m-graph (2 layers) ----
    gemm(mm_f, HID, W_m1, HID, nullptr, p_A, HID, N_M, HID, HID);
    k_gcn_agg<<<wblk(N_M), GB>>>(p_A, e_mm, p_norm_m, p_dinv_m, p_row_m, p_eid_m,
                                 b_m1, p_tmp, HID, N_M, E_MM, 1);
    gemm(p_tmp, HID, W_m2, HID, nullptr, p_A, HID, N_M, HID, HID);
    k_gcn_agg<<<wblk(N_M), GB>>>(p_A, e_mm, p_norm_m, p_dinv_m, p_row_m, p_eid_m,
                                 b_m2, p_xjk, 224, N_M, E_MM, 1);           // x0 (m rows)

    // ---- GCN d-graph (2 layers) ----
    gemm(d_s, HID, W_d1, HID, nullptr, p_A, HID, N_D, HID, HID);
    k_gcn_agg<<<wblk(N_D), GB>>>(p_A, e_dd, p_norm_d, p_dinv_d, p_row_d, p_eid_d,
                                 b_d1, p_tmp + (size_t)N_M * HID, HID, N_D, E_DD, 1);
    gemm(p_tmp + (size_t)N_M * HID, HID, W_d2, HID, nullptr, p_A, HID, N_D, HID, HID);
    k_gcn_agg<<<wblk(N_D), GB>>>(p_A, e_dd, p_norm_d, p_dinv_d, p_row_d, p_eid_d,
                                 b_d2, p_xjk + (size_t)N_M * 224, 224, N_D, E_DD, 1); // x0 (d rows)

    // ---- GATv2 layer 1 (HC=256, C=64) ----
    gemm(p_xjk, 224, Wl1, 256, nullptr, p_A, 256, NTOT, 128, 256);
    gemm(p_xjk, 224, Wr1, 256, nullptr, p_B, 256, NTOT, 128, 256);
    k_gat_logits<256><<<wblk(EG_TOT), GB>>>(p_A, p_B, att1, e_g);
    k_gat_node<256><<<wblk(NTOT), GB>>>(p_A, e_g, bias1, p_xjk + 128, 224, 1); // x1 = elu(.)

    // ---- GATv2 layer 2 (HC=128, C=32) ----
    gemm(p_xjk + 128, 224, Wl2, 128, nullptr, p_A, 128, NTOT, 64, 128);
    gemm(p_xjk + 128, 224, Wr2, 128, nullptr, p_B, 128, NTOT, 64, 128);
    k_gat_logits<128><<<wblk(EG_TOT), GB>>>(p_A, p_B, att2, e_g);
    k_gat_node<128><<<wblk(NTOT), GB>>>(p_A, e_g, bias2, p_xjk + 192, 224, 0); // x2

    // ---- JumpingKnowledge linear: out = [x0|x1|x2] @ Wjk + bjk ----
    gemm(p_xjk, 224, Wjk, 128, bjk, out, 128, NTOT, 224, 128);
}

// round 2
// speedup vs baseline: 1.1640x; 1.1640x over previous
#include <cuda_runtime.h>
#include <math.h>
#include <stdint.h>

// ---------------- problem constants (fixed by the dataset) ----------------
#define N_M   8192
#define N_D   6144
#define NTOT  14336            // N_M + N_D
#define E_MM  131072
#define E_DD  98304
#define E_G   229376
#define EG_TOT (E_G + NTOT)    // real edges + self loops = 243712
#define HID   128
#define TPB   256

// ---------------- scratch (static device globals; no runtime alloc) -------
__device__ float g_ew_m[E_MM],  g_norm_m[E_MM];
__device__ float g_ew_d[E_DD],  g_norm_d[E_DD];
__device__ float g_deg_m[N_M],  g_dinv_m[N_M];
__device__ float g_deg_d[N_D],  g_dinv_d[N_D];
__device__ int   g_cnt_m[N_M],  g_row_m[N_M + 1],  g_cur_m[N_M];
__device__ int   g_eid_m[E_MM];
__device__ int   g_cnt_d[N_D],  g_row_d[N_D + 1],  g_cur_d[N_D];
__device__ int   g_eid_d[E_DD];
__device__ int   g_cnt_g[NTOT], g_row_g[NTOT + 1], g_cur_g[NTOT];
__device__ int   g_eid_g[EG_TOT];
__device__ float g_bufA[(size_t)NTOT * 256];
__device__ float g_bufB[(size_t)NTOT * 256];
__device__ float g_tmp [(size_t)NTOT * 128];
__device__ float g_xjk [(size_t)NTOT * 224];

// ---------------- small helpers ----------------
__device__ __forceinline__ float4 ld4(const float* p) { return *(const float4*)p; }

// ---------------- init ----------------
__global__ void k_init() {
    int i = blockIdx.x * blockDim.x + threadIdx.x;
    if (i < N_M)  { g_deg_m[i] = 1.0f; g_cnt_m[i] = 0; }   // self-loop weight 1
    if (i < N_D)  { g_deg_d[i] = 1.0f; g_cnt_d[i] = 0; }
    if (i < NTOT) { g_cnt_g[i] = 1; }                       // self loop counted in CSR
}

// ---------------- GCN prep: edge-weight gather + degree + count ----------
__global__ void k_gcn_prep(const int* __restrict__ edges, const float* __restrict__ mat,
                           int matN, float* __restrict__ ew, float* __restrict__ deg,
                           int* __restrict__ cnt, int E) {
    int e = blockIdx.x * blockDim.x + threadIdx.x;
    if (e >= E) return;
    int s = edges[e], d = edges[E + e];
    float w = mat[(size_t)s * matN + d];
    ew[e] = w;
    atomicAdd(&deg[d], w);
    atomicAdd(&cnt[d], 1);
}

// combined dinv for both graphs
__global__ void k_dinv2() {
    int i = blockIdx.x * blockDim.x + threadIdx.x;
    if (i < N_M) g_dinv_m[i] = rsqrtf(g_deg_m[i]);
    else if (i < NTOT) g_dinv_d[i - N_M] = rsqrtf(g_deg_d[i - N_M]);
}

// combined norm for both graphs
__global__ void k_norm2(const int* __restrict__ e_mm, const int* __restrict__ e_dd) {
    int e = blockIdx.x * blockDim.x + threadIdx.x;
    if (e < E_MM) {
        g_norm_m[e] = g_dinv_m[e_mm[e]] * g_ew_m[e] * g_dinv_m[e_mm[E_MM + e]];
    } else if (e < E_MM + E_DD) {
        int f = e - E_MM;
        g_norm_d[f] = g_dinv_d[e_dd[f]] * g_ew_d[f] * g_dinv_d[e_dd[E_DD + f]];
    }
}

// ---------------- CSR build ----------------
__global__ void k_scan(const int* __restrict__ cnt, int* __restrict__ row,
                       int* __restrict__ cur, int n) {
    __shared__ int sh[1024];
    int t = threadIdx.x;
    int chunk = (n + 1023) / 1024;
    int lo = t * chunk, hi = min(lo + chunk, n);
    int sum = 0;
    for (int i = lo; i < hi; i++) sum += cnt[i];
    sh[t] = sum;
    __syncthreads();
    for (int off = 1; off < 1024; off <<= 1) {
        int v = 0;
        if (t >= off) v = sh[t - off];
        __syncthreads();
        if (t >= off) sh[t] += v;
        __syncthreads();
    }
    int run = (t == 0) ? 0 : sh[t - 1];
    for (int i = lo; i < hi; i++) { row[i] = run; cur[i] = run; run += cnt[i]; }
    if (t == 1023) row[n] = sh[1023];
}

__global__ void k_fill(const int* __restrict__ edges, int* __restrict__ cur,
                       int* __restrict__ eid, int E) {
    int e = blockIdx.x * blockDim.x + threadIdx.x;
    if (e >= E) return;
    int d = edges[E + e];
    int p = atomicAdd(&cur[d], 1);
    eid[p] = e;
}

__global__ void k_gcount(const int* __restrict__ edges) {
    int e = blockIdx.x * blockDim.x + threadIdx.x;
    if (e >= E_G) return;
    atomicAdd(&g_cnt_g[edges[E_G + e]], 1);
}

__global__ void k_gfill(const int* __restrict__ edges) {
    int e = blockIdx.x * blockDim.x + threadIdx.x;
    if (e >= E_G) return;
    int d = edges[E_G + e];
    int p = atomicAdd(&g_cur_g[d], 1);
    g_eid_g[p] = e;
}

__global__ void k_gfill_self() {
    int i = blockIdx.x * blockDim.x + threadIdx.x;
    if (i >= NTOT) return;
    int p = atomicAdd(&g_cur_g[i], 1);
    g_eid_g[p] = E_G + i;
}

// ---------------- f32 GEMM: C[M,Nc] = A[M,K] @ W[K,Nc] (+bias) ------------
// BM=128, BN=64, BK=32, 256 threads, 8x4 per thread.
// Requires: M%128==0, Nc%64==0, K%32==0 (all dataset shapes satisfy).
__global__ __launch_bounds__(256) void k_gemm(
        const float* __restrict__ A, int lda,
        const float* __restrict__ W, int ldw,
        const float* __restrict__ bias,
        float* __restrict__ C, int ldc,
        int M, int K, int Nc) {
    __shared__ float As[32][132];  // [k][m], 128 + 4 pad (row stride 528B, 16B-aligned)
    __shared__ float Ws[32][64];   // [k][n]
    int tid = threadIdx.x;
    int tx = tid & 15, ty = tid >> 4;
    int row0 = blockIdx.y * 128, col0 = blockIdx.x * 64;
    float acc[8][4] = {};
    for (int k0 = 0; k0 < K; k0 += 32) {
        // A tile 128x32 = 1024 float4, 4 per thread (transposed into As[k][m])
        #pragma unroll
        for (int i = 0; i < 4; i++) {
            int idx = tid + i * 256;
            int r = idx >> 3, c4 = idx & 7;
            float4 v = ld4(A + (size_t)(row0 + r) * lda + k0 + c4 * 4);
            As[c4 * 4 + 0][r] = v.x; As[c4 * 4 + 1][r] = v.y;
            As[c4 * 4 + 2][r] = v.z; As[c4 * 4 + 3][r] = v.w;
        }
        // W tile 32x64 = 512 float4, 2 per thread
        #pragma unroll
        for (int i = 0; i < 2; i++) {
            int idx = tid + i * 256;
            int r = idx >> 4, c4 = idx & 15;
            *(float4*)&Ws[r][c4 * 4] = ld4(W + (size_t)(k0 + r) * ldw + col0 + c4 * 4);
        }
        __syncthreads();
        #pragma unroll
        for (int k = 0; k < 32; k++) {
            float4 a0 = *(float4*)&As[k][ty * 8];
            float4 a1 = *(float4*)&As[k][ty * 8 + 4];
            float4 b  = *(float4*)&Ws[k][tx * 4];
            acc[0][0] += a0.x * b.x; acc[0][1] += a0.x * b.y; acc[0][2] += a0.x * b.z; acc[0][3] += a0.x * b.w;
            acc[1][0] += a0.y * b.x; acc[1][1] += a0.y * b.y; acc[1][2] += a0.y * b.z; acc[1][3] += a0.y * b.w;
            acc[2][0] += a0.z * b.x; acc[2][1] += a0.z * b.y; acc[2][2] += a0.z * b.z; acc[2][3] += a0.z * b.w;
            acc[3][0] += a0.w * b.x; acc[3][1] += a0.w * b.y; acc[3][2] += a0.w * b.z; acc[3][3] += a0.w * b.w;
            acc[4][0] += a1.x * b.x; acc[4][1] += a1.x * b.y; acc[4][2] += a1.x * b.z; acc[4][3] += a1.x * b.w;
            acc[5][0] += a1.y * b.x; acc[5][1] += a1.y * b.y; acc[5][2] += a1.y * b.z; acc[5][3] += a1.y * b.w;
            acc[6][0] += a1.z * b.x; acc[6][1] += a1.z * b.y; acc[6][2] += a1.z * b.z; acc[6][3] += a1.z * b.w;
            acc[7][0] += a1.w * b.x; acc[7][1] += a1.w * b.y; acc[7][2] += a1.w * b.z; acc[7][3] += a1.w * b.w;
        }
        __syncthreads();
    }
    float4 bb = make_float4(0.f, 0.f, 0.f, 0.f);
    if (bias) bb = ld4(bias + col0 + tx * 4);
    #pragma unroll
    for (int i = 0; i < 8; i++) {
        float4 o = make_float4(acc[i][0] + bb.x, acc[i][1] + bb.y,
                               acc[i][2] + bb.z, acc[i][3] + bb.w);
        *(float4*)(C + (size_t)(row0 + ty * 8 + i) * ldc + col0 + tx * 4) = o;
    }
}

// ---------------- GCN aggregate (warp per dst node, 128 channels) ---------
__global__ void k_gcn_agg(const float* __restrict__ h, const int* __restrict__ edges,
                          const float* __restrict__ nrm, const float* __restrict__ dinv,
                          const int* __restrict__ row, const int* __restrict__ eid,
                          const float* __restrict__ bias,
                          float* __restrict__ out, int ldout, int n, int E, int relu) {
    int w = (blockIdx.x * blockDim.x + threadIdx.x) >> 5;
    int lane = threadIdx.x & 31;
    if (w >= n) return;
    int rs = row[w], re = row[w + 1];
    float4 acc = make_float4(0.f, 0.f, 0.f, 0.f);
    for (int j = rs; j < re; j++) {
        int e = eid[j];
        float nm = nrm[e];
        int s = edges[e];
        float4 v = ld4(h + (size_t)s * HID + lane * 4);
        acc.x += nm * v.x; acc.y += nm * v.y; acc.z += nm * v.z; acc.w += nm * v.w;
    }
    float di = dinv[w];
    float sw = di * di;
    float4 v = ld4(h + (size_t)w * HID + lane * 4);
    acc.x += sw * v.x; acc.y += sw * v.y; acc.z += sw * v.z; acc.w += sw * v.w;
    float4 b = ld4(bias + lane * 4);
    acc.x += b.x; acc.y += b.y; acc.z += b.z; acc.w += b.w;
    if (relu) {
        acc.x = fmaxf(acc.x, 0.f); acc.y = fmaxf(acc.y, 0.f);
        acc.z = fmaxf(acc.z, 0.f); acc.w = fmaxf(acc.w, 0.f);
    }
    *(float4*)(out + (size_t)w * ldout + lane * 4) = acc;
}

// ---------------- Fused GATv2 (warp per dst node, online softmax) ---------
// Logits computed inline: dst row xr[i] cached in registers; each edge's
// xl[src] read ONCE and used for both the logit and the numerator.
// Lane owns CH = HC/32 contiguous channels; 8-lane groups cover one head.
template <int HC>
__global__ void k_gat_fused(const float* __restrict__ xl, const float* __restrict__ xr,
                            const float* __restrict__ att, const int* __restrict__ edges,
                            const float* __restrict__ bias,
                            float* __restrict__ out, int ldout, int elu) {
    const int CH = HC / 32;
    int i = (blockIdx.x * blockDim.x + threadIdx.x) >> 5;
    int lane = threadIdx.x & 31;
    if (i >= NTOT) return;
    int rs = g_row_g[i], re = g_row_g[i + 1];

    float attv[CH], xrv[CH];
    #pragma unroll
    for (int k = 0; k < CH; k += 4) {
        float4 a = ld4(att + lane * CH + k);
        attv[k] = a.x; attv[k + 1] = a.y; attv[k + 2] = a.z; attv[k + 3] = a.w;
        float4 r = ld4(xr + (size_t)i * HC + lane * CH + k);
        xrv[k] = r.x; xrv[k + 1] = r.y; xrv[k + 2] = r.z; xrv[k + 3] = r.w;
    }

    float m = -1e30f, den = 0.f;
    float num[CH];
    #pragma unroll
    for (int k = 0; k < CH; k++) num[k] = 0.f;

    for (int j = rs; j < re; j++) {
        int e = g_eid_g[j];
        int s = (e < E_G) ? edges[e] : (e - E_G);
        float xlv[CH];
        float p = 0.f;
        #pragma unroll
        for (int k = 0; k < CH; k += 4) {
            float4 v = ld4(xl + (size_t)s * HC + lane * CH + k);
            xlv[k] = v.x; xlv[k + 1] = v.y; xlv[k + 2] = v.z; xlv[k + 3] = v.w;
        }
        #pragma unroll
        for (int k = 0; k < CH; k++) {
            float t = xlv[k] + xrv[k];
            t = t > 0.f ? t : 0.2f * t;
            p += t * attv[k];
        }
        // reduce over the 8 lanes of this head -> all 8 lanes get the logit
        p += __shfl_xor_sync(0xffffffffu, p, 1);
        p += __shfl_xor_sync(0xffffffffu, p, 2);
        p += __shfl_xor_sync(0xffffffffu, p, 4);
        // online softmax update
        float mn = fmaxf(m, p);
        float c  = __expf(m - mn) == 0.f && m == -1e30f ? 0.f : expf(m - mn);
        float ex = expf(p - mn);
        den = den * c + ex;
        #pragma unroll
        for (int k = 0; k < CH; k++) num[k] = num[k] * c + ex * xlv[k];
        m = mn;
    }

    float inv = 0.25f / den;   // includes 1/H head-mean
    #pragma unroll
    for (int k = 0; k < CH; k++) {
        float v = num[k] * inv;
        v += __shfl_xor_sync(0xffffffffu, v, 8);
        v += __shfl_xor_sync(0xffffffffu, v, 16);
        num[k] = v;
    }
    if (lane < 8) {
        float o[CH];
        #pragma unroll
        for (int k = 0; k < CH; k++) {
            float v = num[k] + bias[lane * CH + k];
            if (elu) v = v > 0.f ? v : expm1f(v);
            o[k] = v;
        }
        float* po = out + (size_t)i * ldout + lane * CH;
        #pragma unroll
        for (int k = 0; k < CH; k += 4)
            *(float4*)(po + k) = make_float4(o[k], o[k + 1], o[k + 2], o[k + 3]);
    }
}

// ---------------- host orchestration ----------------
static inline void gemm(const float* A, int lda, const float* W, int ldw,
                        const float* bias, float* C, int ldc, int M, int K, int Nc) {
    dim3 grid(Nc / 64, M / 128);
    k_gemm<<<grid, 256>>>(A, lda, W, ldw, bias, C, ldc, M, K, Nc);
}

extern "C" void kernel_launch(void* const* d_in, const int* in_sizes, int n_in,
                              void* d_out, int out_size) {
    const float* mm_f = (const float*)d_in[0];
    const float* d_s  = (const float*)d_in[1];
    const float* msM  = (const float*)d_in[2];
    const float* dsM  = (const float*)d_in[3];
    const int*   e_mm = (const int*)d_in[4];
    const int*   e_dd = (const int*)d_in[5];
    const int*   e_g  = (const int*)d_in[6];
    const float* W_m1 = (const float*)d_in[7];  const float* b_m1 = (const float*)d_in[8];
    const float* W_m2 = (const float*)d_in[9];  const float* b_m2 = (const float*)d_in[10];
    const float* W_d1 = (const float*)d_in[11]; const float* b_d1 = (const float*)d_in[12];
    const float* W_d2 = (const float*)d_in[13]; const float* b_d2 = (const float*)d_in[14];
    const float* Wl1  = (const float*)d_in[15]; const float* Wr1  = (const float*)d_in[16];
    const float* att1 = (const float*)d_in[17]; const float* bias1 = (const float*)d_in[18];
    const float* Wl2  = (const float*)d_in[19]; const float* Wr2  = (const float*)d_in[20];
    const float* att2 = (const float*)d_in[21]; const float* bias2 = (const float*)d_in[22];
    const float* Wjk  = (const float*)d_in[23]; const float* bjk  = (const float*)d_in[24];
    float* out = (float*)d_out;

    float *p_ew_m, *p_deg_m, *p_dinv_m, *p_norm_m;
    float *p_ew_d, *p_deg_d, *p_dinv_d, *p_norm_d;
    int *p_cnt_m, *p_row_m, *p_cur_m, *p_eid_m;
    int *p_cnt_d, *p_row_d, *p_cur_d, *p_eid_d;
    int *p_cnt_g, *p_row_g, *p_cur_g;
    float *p_A, *p_B, *p_tmp, *p_xjk;
    cudaGetSymbolAddress((void**)&p_ew_m,  g_ew_m);   cudaGetSymbolAddress((void**)&p_norm_m, g_norm_m);
    cudaGetSymbolAddress((void**)&p_ew_d,  g_ew_d);   cudaGetSymbolAddress((void**)&p_norm_d, g_norm_d);
    cudaGetSymbolAddress((void**)&p_deg_m, g_deg_m);  cudaGetSymbolAddress((void**)&p_dinv_m, g_dinv_m);
    cudaGetSymbolAddress((void**)&p_deg_d, g_deg_d);  cudaGetSymbolAddress((void**)&p_dinv_d, g_dinv_d);
    cudaGetSymbolAddress((void**)&p_cnt_m, g_cnt_m);  cudaGetSymbolAddress((void**)&p_row_m,  g_row_m);
    cudaGetSymbolAddress((void**)&p_cur_m, g_cur_m);  cudaGetSymbolAddress((void**)&p_eid_m,  g_eid_m);
    cudaGetSymbolAddress((void**)&p_cnt_d, g_cnt_d);  cudaGetSymbolAddress((void**)&p_row_d,  g_row_d);
    cudaGetSymbolAddress((void**)&p_cur_d, g_cur_d);  cudaGetSymbolAddress((void**)&p_eid_d,  g_eid_d);
    cudaGetSymbolAddress((void**)&p_cnt_g, g_cnt_g);  cudaGetSymbolAddress((void**)&p_row_g,  g_row_g);
    cudaGetSymbolAddress((void**)&p_cur_g, g_cur_g);
    cudaGetSymbolAddress((void**)&p_A,   g_bufA);     cudaGetSymbolAddress((void**)&p_B,   g_bufB);
    cudaGetSymbolAddress((void**)&p_tmp, g_tmp);      cudaGetSymbolAddress((void**)&p_xjk, g_xjk);

    const int GB = TPB;
    auto blk = [](int n) { return (n + TPB - 1) / TPB; };
    auto wblk = [](int nwarps) { return (nwarps * 32 + TPB - 1) / TPB; };

    // ---- CSR / normalization prep ----
    k_init<<<blk(NTOT), GB>>>();
    k_gcn_prep<<<blk(E_MM), GB>>>(e_mm, msM, N_M, p_ew_m, p_deg_m, p_cnt_m, E_MM);
    k_gcn_prep<<<blk(E_DD), GB>>>(e_dd, dsM, N_D, p_ew_d, p_deg_d, p_cnt_d, E_DD);
    k_gcount<<<blk(E_G), GB>>>(e_g);
    k_dinv2<<<blk(NTOT), GB>>>();
    k_norm2<<<blk(E_MM + E_DD), GB>>>(e_mm, e_dd);
    k_scan<<<1, 1024>>>(p_cnt_m, p_row_m, p_cur_m, N_M);
    k_scan<<<1, 1024>>>(p_cnt_d, p_row_d, p_cur_d, N_D);
    k_scan<<<1, 1024>>>(p_cnt_g, p_row_g, p_cur_g, NTOT);
    k_fill<<<blk(E_MM), GB>>>(e_mm, p_cur_m, p_eid_m, E_MM);
    k_fill<<<blk(E_DD), GB>>>(e_dd, p_cur_d, p_eid_d, E_DD);
    k_gfill<<<blk(E_G), GB>>>(e_g);
    k_gfill_self<<<blk(NTOT), GB>>>();

    // ---- GCN m-graph (2 layers) ----
    gemm(mm_f, HID, W_m1, HID, nullptr, p_A, HID, N_M, HID, HID);
    k_gcn_agg<<<wblk(N_M), GB>>>(p_A, e_mm, p_norm_m, p_dinv_m, p_row_m, p_eid_m,
                                 b_m1, p_tmp, HID, N_M, E_MM, 1);
    gemm(p_tmp, HID, W_m2, HID, nullptr, p_A, HID, N_M, HID, HID);
    k_gcn_agg<<<wblk(N_M), GB>>>(p_A, e_mm, p_norm_m, p_dinv_m, p_row_m, p_eid_m,
                                 b_m2, p_xjk, 224, N_M, E_MM, 1);           // x0 (m rows)

    // ---- GCN d-graph (2 layers) ----
    gemm(d_s, HID, W_d1, HID, nullptr, p_A, HID, N_D, HID, HID);
    k_gcn_agg<<<wblk(N_D), GB>>>(p_A, e_dd, p_norm_d, p_dinv_d, p_row_d, p_eid_d,
                                 b_d1, p_tmp + (size_t)N_M * HID, HID, N_D, E_DD, 1);
    gemm(p_tmp + (size_t)N_M * HID, HID, W_d2, HID, nullptr, p_A, HID, N_D, HID, HID);
    k_gcn_agg<<<wblk(N_D), GB>>>(p_A, e_dd, p_norm_d, p_dinv_d, p_row_d, p_eid_d,
                                 b_d2, p_xjk + (size_t)N_M * 224, 224, N_D, E_DD, 1); // x0 (d rows)

    // ---- GATv2 layer 1 (HC=256, C=64) ----
    gemm(p_xjk, 224, Wl1, 256, nullptr, p_A, 256, NTOT, 128, 256);
    gemm(p_xjk, 224, Wr1, 256, nullptr, p_B, 256, NTOT, 128, 256);
    k_gat_fused<256><<<wblk(NTOT), GB>>>(p_A, p_B, att1, e_g, bias1, p_xjk + 128, 224, 1);

    // ---- GATv2 layer 2 (HC=128, C=32) ----
    gemm(p_xjk + 128, 224, Wl2, 128, nullptr, p_A, 128, NTOT, 64, 128);
    gemm(p_xjk + 128, 224, Wr2, 128, nullptr, p_B, 128, NTOT, 64, 128);
    k_gat_fused<128><<<wblk(NTOT), GB>>>(p_A, p_B, att2, e_g, bias2, p_xjk + 192, 224, 0);

    // ---- JumpingKnowledge linear: out = [x0|x1|x2] @ Wjk + bjk ----
    gemm(p_xjk, 224, Wjk, 128, bjk, out, 128, NTOT, 224, 128);
}

// round 4
// speedup vs baseline: 1.4555x; 1.2504x over previous
#include <cuda_runtime.h>
#include <math.h>
#include <stdint.h>

// ---------------- problem constants (fixed by the dataset) ----------------
#define N_M   8192
#define N_D   6144
#define NTOT  14336            // N_M + N_D
#define E_MM  131072
#define E_DD  98304
#define E_G   229376
#define EG_TOT (E_G + NTOT)    // real edges + self loops = 243712
#define HID   128
#define TPB   256

// ---------------- scratch (static device globals; no runtime alloc) -------
__device__ float g_ew_m[E_MM],  g_norm_m[E_MM];
__device__ float g_ew_d[E_DD],  g_norm_d[E_DD];
__device__ float g_deg_m[N_M],  g_dinv_m[N_M];
__device__ float g_deg_d[N_D],  g_dinv_d[N_D];
__device__ int   g_cnt_m[N_M],  g_row_m[N_M + 1],  g_cur_m[N_M];
__device__ int   g_src_m[E_MM];  __device__ float g_w_m[E_MM];
__device__ int   g_cnt_d[N_D],  g_row_d[N_D + 1],  g_cur_d[N_D];
__device__ int   g_src_d[E_DD];  __device__ float g_w_d[E_DD];
__device__ int   g_cnt_g[NTOT], g_row_g[NTOT + 1], g_cur_g[NTOT];
__device__ int   g_src_g[EG_TOT];
__device__ float g_bufA[(size_t)NTOT * 256];
__device__ float g_bufB[(size_t)NTOT * 256];
__device__ float g_tmp [(size_t)NTOT * 128];
__device__ float g_xjk [(size_t)NTOT * 224];

__device__ __forceinline__ float4 ld4(const float* p) { return *(const float4*)p; }

// ---------------- init ----------------
__global__ void k_init() {
    int i = blockIdx.x * blockDim.x + threadIdx.x;
    if (i < N_M)  { g_deg_m[i] = 1.0f; g_cnt_m[i] = 0; }   // self-loop weight 1
    if (i < N_D)  { g_deg_d[i] = 1.0f; g_cnt_d[i] = 0; }
    if (i < NTOT) { g_cnt_g[i] = 1; }                       // self loop pre-counted
}

// ---------------- combined edge prep (both GCN graphs + GAT count) --------
__global__ void k_prep_all(const int* __restrict__ e_mm, const float* __restrict__ msM,
                           const int* __restrict__ e_dd, const float* __restrict__ dsM,
                           const int* __restrict__ e_g) {
    int i = blockIdx.x * blockDim.x + threadIdx.x;
    if (i < E_MM) {
        int s = e_mm[i], d = e_mm[E_MM + i];
        float w = msM[(size_t)s * N_M + d];
        g_ew_m[i] = w;
        atomicAdd(&g_deg_m[d], w);
        atomicAdd(&g_cnt_m[d], 1);
    } else if (i < E_MM + E_DD) {
        int f = i - E_MM;
        int s = e_dd[f], d = e_dd[E_DD + f];
        float w = dsM[(size_t)s * N_D + d];
        g_ew_d[f] = w;
        atomicAdd(&g_deg_d[d], w);
        atomicAdd(&g_cnt_d[d], 1);
    } else if (i < E_MM + E_DD + E_G) {
        int f = i - E_MM - E_DD;
        atomicAdd(&g_cnt_g[e_g[E_G + f]], 1);
    }
}

__global__ void k_dinv2() {
    int i = blockIdx.x * blockDim.x + threadIdx.x;
    if (i < N_M) g_dinv_m[i] = rsqrtf(g_deg_m[i]);
    else if (i < NTOT) g_dinv_d[i - N_M] = rsqrtf(g_deg_d[i - N_M]);
}

__global__ void k_norm2(const int* __restrict__ e_mm, const int* __restrict__ e_dd) {
    int e = blockIdx.x * blockDim.x + threadIdx.x;
    if (e < E_MM) {
        g_norm_m[e] = g_dinv_m[e_mm[e]] * g_ew_m[e] * g_dinv_m[e_mm[E_MM + e]];
    } else if (e < E_MM + E_DD) {
        int f = e - E_MM;
        g_norm_d[f] = g_dinv_d[e_dd[f]] * g_ew_d[f] * g_dinv_d[e_dd[E_DD + f]];
    }
}

// ---------------- 3 scans in one launch (blockIdx picks the graph) --------
__global__ void k_scan3() {
    __shared__ int sh[1024];
    const int* cnt; int* row; int* cur; int n;
    if (blockIdx.x == 0)      { cnt = g_cnt_m; row = g_row_m; cur = g_cur_m; n = N_M; }
    else if (blockIdx.x == 1) { cnt = g_cnt_d; row = g_row_d; cur = g_cur_d; n = N_D; }
    else                      { cnt = g_cnt_g; row = g_row_g; cur = g_cur_g; n = NTOT; }
    int t = threadIdx.x;
    int chunk = (n + 1023) / 1024;
    int lo = t * chunk, hi = min(lo + chunk, n);
    int sum = 0;
    for (int i = lo; i < hi; i++) sum += cnt[i];
    sh[t] = sum;
    __syncthreads();
    for (int off = 1; off < 1024; off <<= 1) {
        int v = 0;
        if (t >= off) v = sh[t - off];
        __syncthreads();
        if (t >= off) sh[t] += v;
        __syncthreads();
    }
    int run = (t == 0) ? 0 : sh[t - 1];
    for (int i = lo; i < hi; i++) { row[i] = run; cur[i] = run; run += cnt[i]; }
    if (t == 1023) row[n] = sh[1023];
}

// ---------------- combined CSR fill (src + weight stored CSR-ordered) -----
__global__ void k_fill_all(const int* __restrict__ e_mm, const int* __restrict__ e_dd,
                           const int* __restrict__ e_g) {
    int i = blockIdx.x * blockDim.x + threadIdx.x;
    if (i < E_MM) {
        int d = e_mm[E_MM + i];
        int p = atomicAdd(&g_cur_m[d], 1);
        g_src_m[p] = e_mm[i];
        g_w_m[p] = g_norm_m[i];
    } else if (i < E_MM + E_DD) {
        int f = i - E_MM;
        int d = e_dd[E_DD + f];
        int p = atomicAdd(&g_cur_d[d], 1);
        g_src_d[p] = e_dd[f];
        g_w_d[p] = g_norm_d[f];
    } else if (i < E_MM + E_DD + E_G) {
        int f = i - E_MM - E_DD;
        int d = e_g[E_G + f];
        int p = atomicAdd(&g_cur_g[d], 1);
        g_src_g[p] = e_g[f];
    } else if (i < E_MM + E_DD + E_G + NTOT) {
        int f = i - E_MM - E_DD - E_G;     // self loop
        int p = atomicAdd(&g_cur_g[f], 1);
        g_src_g[p] = f;
    }
}

// ---------------- f32 GEMM: 128x128x32 tiles, 8x8/thread, dual-task/dual-W -
struct GTask { const float* A; const float* W1; const float* W2; float* C1; float* C2; int M; };

__global__ __launch_bounds__(256) void k_gemm(
        GTask ta, GTask tb,
        int lda, int Nsplit, int ldw, const float* bias, int ldc, int K) {
    __shared__ float As[32][132];   // [k][m], padded
    __shared__ float Ws[32][128];   // [k][n]
    GTask t = (blockIdx.z == 0) ? ta : tb;
    int row0 = blockIdx.y * 128;
    if (row0 >= t.M) return;
    int col0 = blockIdx.x * 128;
    const float* Wb; float* Cb;
    if (col0 < Nsplit) { Wb = t.W1 + col0;            Cb = t.C1 + col0; }
    else               { Wb = t.W2 + (col0 - Nsplit); Cb = t.C2 + (col0 - Nsplit); }

    int tid = threadIdx.x;
    int tx = tid & 15, ty = tid >> 4;        // 16x16 thread grid, 8x8 each
    float acc[8][8] = {};

    for (int k0 = 0; k0 < K; k0 += 32) {
        #pragma unroll
        for (int i = 0; i < 4; i++) {
            int idx = tid + i * 256;
            int r = idx >> 3, c4 = idx & 7;
            float4 v = ld4(t.A + (size_t)(row0 + r) * lda + k0 + c4 * 4);
            As[c4 * 4 + 0][r] = v.x; As[c4 * 4 + 1][r] = v.y;
            As[c4 * 4 + 2][r] = v.z; As[c4 * 4 + 3][r] = v.w;
        }
        #pragma unroll
        for (int i = 0; i < 4; i++) {
            int idx = tid + i * 256;
            int r = idx >> 5, c4 = idx & 31;
            *(float4*)&Ws[r][c4 * 4] = ld4(Wb + (size_t)(k0 + r) * ldw + c4 * 4);
        }
        __syncthreads();
        #pragma unroll 16
        for (int k = 0; k < 32; k++) {
            float a[8], b[8];
            *(float4*)&a[0] = *(float4*)&As[k][ty * 8];
            *(float4*)&a[4] = *(float4*)&As[k][ty * 8 + 4];
            *(float4*)&b[0] = *(float4*)&Ws[k][tx * 8];
            *(float4*)&b[4] = *(float4*)&Ws[k][tx * 8 + 4];
            #pragma unroll
            for (int i = 0; i < 8; i++)
                #pragma unroll
                for (int j = 0; j < 8; j++)
                    acc[i][j] += a[i] * b[j];
        }
        __syncthreads();
    }

    float bv[8] = {};
    if (bias) {
        *(float4*)&bv[0] = ld4(bias + col0 + tx * 8);
        *(float4*)&bv[4] = ld4(bias + col0 + tx * 8 + 4);
    }
    #pragma unroll
    for (int i = 0; i < 8; i++) {
        float* pc = Cb + (size_t)(row0 + ty * 8 + i) * ldc + tx * 8;
        *(float4*)pc       = make_float4(acc[i][0] + bv[0], acc[i][1] + bv[1],
                                         acc[i][2] + bv[2], acc[i][3] + bv[3]);
        *(float4*)(pc + 4) = make_float4(acc[i][4] + bv[4], acc[i][5] + bv[5],
                                         acc[i][6] + bv[6], acc[i][7] + bv[7]);
    }
}

// ---------------- GCN aggregate, both graphs in one launch ----------------
// h layout: rows [0,N_M) = m-graph features, rows [N_M,NTOT) = d-graph.
__global__ void k_gcn_agg2(const float* __restrict__ h,
                           const float* __restrict__ bias_m, const float* __restrict__ bias_d,
                           float* __restrict__ out_m, float* __restrict__ out_d,
                           int ldm, int ldd) {
    int w = (blockIdx.x * blockDim.x + threadIdx.x) >> 5;
    int lane = threadIdx.x & 31;
    if (w >= NTOT) return;
    const int* row; const int* src; const float* wcs; const float* bias;
    const float* hb; const float* dinv; float* po; int node;
    if (w < N_M) {
        node = w; row = g_row_m; src = g_src_m; wcs = g_w_m; bias = bias_m;
        hb = h; dinv = g_dinv_m;
        po = out_m + (size_t)w * ldm + lane * 4;                  // FIX: + lane*4
    } else {
        node = w - N_M; row = g_row_d; src = g_src_d; wcs = g_w_d; bias = bias_d;
        hb = h + (size_t)N_M * HID; dinv = g_dinv_d;
        po = out_d + (size_t)(w - N_M) * ldd + lane * 4;          // FIX: + lane*4
    }
    int rs = row[node], re = row[node + 1];
    float4 acc = make_float4(0.f, 0.f, 0.f, 0.f);
    for (int j = rs; j < re; j++) {
        int s = src[j];
        float nm = wcs[j];
        float4 v = ld4(hb + (size_t)s * HID + lane * 4);
        acc.x += nm * v.x; acc.y += nm * v.y; acc.z += nm * v.z; acc.w += nm * v.w;
    }
    float di = dinv[node];
    float sw = di * di;
    float4 v = ld4(hb + (size_t)node * HID + lane * 4);
    acc.x += sw * v.x; acc.y += sw * v.y; acc.z += sw * v.z; acc.w += sw * v.w;
    float4 b = ld4(bias + lane * 4);
    acc.x = fmaxf(acc.x + b.x, 0.f); acc.y = fmaxf(acc.y + b.y, 0.f);
    acc.z = fmaxf(acc.z + b.z, 0.f); acc.w = fmaxf(acc.w + b.w, 0.f);
    *(float4*)po = acc;
}

// ---------------- Fused GATv2 (warp per dst node, online softmax) ---------
template <int HC>
__global__ void k_gat_fused(const float* __restrict__ xl, const float* __restrict__ xr,
                            const float* __restrict__ att,
                            const float* __restrict__ bias,
                            float* __restrict__ out, int ldout, int elu) {
    const int CH = HC / 32;
    int i = (blockIdx.x * blockDim.x + threadIdx.x) >> 5;
    int lane = threadIdx.x & 31;
    if (i >= NTOT) return;
    int rs = g_row_g[i], re = g_row_g[i + 1];

    float attv[CH], xrv[CH];
    #pragma unroll
    for (int k = 0; k < CH; k += 4) {
        float4 a = ld4(att + lane * CH + k);
        attv[k] = a.x; attv[k + 1] = a.y; attv[k + 2] = a.z; attv[k + 3] = a.w;
        float4 r = ld4(xr + (size_t)i * HC + lane * CH + k);
        xrv[k] = r.x; xrv[k + 1] = r.y; xrv[k + 2] = r.z; xrv[k + 3] = r.w;
    }

    float m = -1e30f, den = 0.f;
    float num[CH];
    #pragma unroll
    for (int k = 0; k < CH; k++) num[k] = 0.f;

    for (int j = rs; j < re; j++) {
        int s = g_src_g[j];
        float xlv[CH];
        float p = 0.f;
        #pragma unroll
        for (int k = 0; k < CH; k += 4) {
            float4 v = ld4(xl + (size_t)s * HC + lane * CH + k);
            xlv[k] = v.x; xlv[k + 1] = v.y; xlv[k + 2] = v.z; xlv[k + 3] = v.w;
        }
        #pragma unroll
        for (int k = 0; k < CH; k++) {
            float t = xlv[k] + xrv[k];
            t = t > 0.f ? t : 0.2f * t;
            p += t * attv[k];
        }
        p += __shfl_xor_sync(0xffffffffu, p, 1);
        p += __shfl_xor_sync(0xffffffffu, p, 2);
        p += __shfl_xor_sync(0xffffffffu, p, 4);
        float mn = fmaxf(m, p);
        float c  = expf(m - mn);      // first iter: exp(-huge) = 0
        float ex = expf(p - mn);
        den = den * c + ex;
        #pragma unroll
        for (int k = 0; k < CH; k++) num[k] = num[k] * c + ex * xlv[k];
        m = mn;
    }

    float inv = 0.25f / den;   // includes 1/H head-mean
    #pragma unroll
    for (int k = 0; k < CH; k++) {
        float v = num[k] * inv;
        v += __shfl_xor_sync(0xffffffffu, v, 8);
        v += __shfl_xor_sync(0xffffffffu, v, 16);
        num[k] = v;
    }
    if (lane < 8) {
        float o[CH];
        #pragma unroll
        for (int k = 0; k < CH; k++) {
            float v = num[k] + bias[lane * CH + k];
            if (elu) v = v > 0.f ? v : expm1f(v);
            o[k] = v;
        }
        float* po = out + (size_t)i * ldout + lane * CH;
        #pragma unroll
        for (int k = 0; k < CH; k += 4)
            *(float4*)(po + k) = make_float4(o[k], o[k + 1], o[k + 2], o[k + 3]);
    }
}

// ---------------- host orchestration ----------------
extern "C" void kernel_launch(void* const* d_in, const int* in_sizes, int n_in,
                              void* d_out, int out_size) {
    const float* mm_f = (const float*)d_in[0];
    const float* d_s  = (const float*)d_in[1];
    const float* msM  = (const float*)d_in[2];
    const float* dsM  = (const float*)d_in[3];
    const int*   e_mm = (const int*)d_in[4];
    const int*   e_dd = (const int*)d_in[5];
    const int*   e_g  = (const int*)d_in[6];
    const float* W_m1 = (const float*)d_in[7];  const float* b_m1 = (const float*)d_in[8];
    const float* W_m2 = (const float*)d_in[9];  const float* b_m2 = (const float*)d_in[10];
    const float* W_d1 = (const float*)d_in[11]; const float* b_d1 = (const float*)d_in[12];
    const float* W_d2 = (const float*)d_in[13]; const float* b_d2 = (const float*)d_in[14];
    const float* Wl1  = (const float*)d_in[15]; const float* Wr1  = (const float*)d_in[16];
    const float* att1 = (const float*)d_in[17]; const float* bias1 = (const float*)d_in[18];
    const float* Wl2  = (const float*)d_in[19]; const float* Wr2  = (const float*)d_in[20];
    const float* att2 = (const float*)d_in[21]; const float* bias2 = (const float*)d_in[22];
    const float* Wjk  = (const float*)d_in[23]; const float* bjk  = (const float*)d_in[24];
    float* out = (float*)d_out;

    float *p_A, *p_B, *p_tmp, *p_xjk;
    cudaGetSymbolAddress((void**)&p_A,   g_bufA);
    cudaGetSymbolAddress((void**)&p_B,   g_bufB);
    cudaGetSymbolAddress((void**)&p_tmp, g_tmp);
    cudaGetSymbolAddress((void**)&p_xjk, g_xjk);

    const int GB = TPB;
    auto blk = [](int n) { return (n + TPB - 1) / TPB; };
    auto wblk = [](int nwarps) { return (nwarps * 32 + TPB - 1) / TPB; };

    // ---- prep: 6 launches ----
    k_init<<<blk(NTOT), GB>>>();
    k_prep_all<<<blk(E_MM + E_DD + E_G), GB>>>(e_mm, msM, e_dd, dsM, e_g);
    k_dinv2<<<blk(NTOT), GB>>>();
    k_norm2<<<blk(E_MM + E_DD), GB>>>(e_mm, e_dd);
    k_scan3<<<3, 1024>>>();
    k_fill_all<<<blk(E_MM + E_DD + E_G + NTOT), GB>>>(e_mm, e_dd, e_g);

    // ---- GCN layer 1 (m + d fused via blockIdx.z) ----
    {
        GTask ta = { mm_f, W_m1, W_m1, p_A,                      p_A,                      N_M };
        GTask tb = { d_s,  W_d1, W_d1, p_A + (size_t)N_M * HID,  p_A + (size_t)N_M * HID,  N_D };
        k_gemm<<<dim3(1, N_M / 128, 2), 256>>>(ta, tb, HID, 128, HID, nullptr, HID, HID);
    }
    k_gcn_agg2<<<wblk(NTOT), GB>>>(p_A, b_m1, b_d1, p_tmp, p_tmp + (size_t)N_M * HID, HID, HID);

    // ---- GCN layer 2 ----
    {
        GTask ta = { p_tmp,                      W_m2, W_m2, p_A,                     p_A,                     N_M };
        GTask tb = { p_tmp + (size_t)N_M * HID,  W_d2, W_d2, p_A + (size_t)N_M * HID, p_A + (size_t)N_M * HID, N_D };
        k_gemm<<<dim3(1, N_M / 128, 2), 256>>>(ta, tb, HID, 128, HID, nullptr, HID, HID);
    }
    // x0 = relu(gcn2) into xjk cols [0,128)
    k_gcn_agg2<<<wblk(NTOT), GB>>>(p_A, b_m2, b_d2, p_xjk, p_xjk + (size_t)N_M * 224, 224, 224);

    // ---- GATv2 layer 1: xl|xr in ONE dual-W GEMM (K=128, Nc=256+256) ----
    {
        GTask ta = { p_xjk, Wl1, Wr1, p_A, p_B, NTOT };
        k_gemm<<<dim3(4, NTOT / 128, 1), 256>>>(ta, ta, 224, 256, 256, nullptr, 256, 128);
    }
    k_gat_fused<256><<<wblk(NTOT), GB>>>(p_A, p_B, att1, bias1, p_xjk + 128, 224, 1);

    // ---- GATv2 layer 2 (K=64, Nc=128+128) ----
    {
        GTask ta = { p_xjk + 128, Wl2, Wr2, p_A, p_B, NTOT };
        k_gemm<<<dim3(2, NTOT / 128, 1), 256>>>(ta, ta, 224, 128, 128, nullptr, 128, 64);
    }
    k_gat_fused<128><<<wblk(NTOT), GB>>>(p_A, p_B, att2, bias2, p_xjk + 192, 224, 0);

    // ---- JumpingKnowledge linear: out = [x0|x1|x2] @ Wjk + bjk ----
    {
        GTask ta = { p_xjk, Wjk, Wjk, out, out, NTOT };
        k_gemm<<<dim3(1, NTOT / 128, 1), 256>>>(ta, ta, 224, 128, 128, bjk, 128, 224);
    }
}

// round 5
// speedup vs baseline: 1.5566x; 1.0695x over previous
#include <cuda_runtime.h>
#include <math.h>
#include <stdint.h>

// ---------------- problem constants (fixed by the dataset) ----------------
#define N_M   8192
#define N_D   6144
#define NTOT  14336            // N_M + N_D
#define E_MM  131072
#define E_DD  98304
#define E_G   229376
#define EG_TOT (E_G + NTOT)    // real edges + self loops = 243712
#define HID   128
#define TPB   256

// ---------------- scratch (static device globals; no runtime alloc) -------
__device__ float g_ew_m[E_MM],  g_norm_m[E_MM];
__device__ float g_ew_d[E_DD],  g_norm_d[E_DD];
__device__ float g_deg_m[N_M],  g_dinv_m[N_M];
__device__ float g_deg_d[N_D],  g_dinv_d[N_D];
__device__ int   g_cnt_m[N_M],  g_row_m[N_M + 1],  g_cur_m[N_M];
__device__ int   g_src_m[E_MM];  __device__ float g_w_m[E_MM];
__device__ int   g_cnt_d[N_D],  g_row_d[N_D + 1],  g_cur_d[N_D];
__device__ int   g_src_d[E_DD];  __device__ float g_w_d[E_DD];
__device__ int   g_cnt_g[NTOT], g_row_g[NTOT + 1], g_cur_g[NTOT];
__device__ int   g_src_g[EG_TOT];
__device__ float g_bufA[(size_t)NTOT * 256];
__device__ float g_bufB[(size_t)NTOT * 256];
__device__ float g_tmp [(size_t)NTOT * 128];
__device__ float g_xjk [(size_t)NTOT * 224];

__device__ __forceinline__ float4 ld4(const float* p) { return *(const float4*)p; }

// ---------------- init ----------------
__global__ void k_init() {
    int i = blockIdx.x * blockDim.x + threadIdx.x;
    if (i < N_M)  { g_deg_m[i] = 1.0f; g_cnt_m[i] = 0; }   // self-loop weight 1
    if (i < N_D)  { g_deg_d[i] = 1.0f; g_cnt_d[i] = 0; }
    if (i < NTOT) { g_cnt_g[i] = 1; }                       // self loop pre-counted
}

// ---------------- combined edge prep (both GCN graphs + GAT count) --------
__global__ void k_prep_all(const int* __restrict__ e_mm, const float* __restrict__ msM,
                           const int* __restrict__ e_dd, const float* __restrict__ dsM,
                           const int* __restrict__ e_g) {
    int i = blockIdx.x * blockDim.x + threadIdx.x;
    if (i < E_MM) {
        int s = e_mm[i], d = e_mm[E_MM + i];
        float w = msM[(size_t)s * N_M + d];
        g_ew_m[i] = w;
        atomicAdd(&g_deg_m[d], w);
        atomicAdd(&g_cnt_m[d], 1);
    } else if (i < E_MM + E_DD) {
        int f = i - E_MM;
        int s = e_dd[f], d = e_dd[E_DD + f];
        float w = dsM[(size_t)s * N_D + d];
        g_ew_d[f] = w;
        atomicAdd(&g_deg_d[d], w);
        atomicAdd(&g_cnt_d[d], 1);
    } else if (i < E_MM + E_DD + E_G) {
        int f = i - E_MM - E_DD;
        atomicAdd(&g_cnt_g[e_g[E_G + f]], 1);
    }
}

__global__ void k_dinv2() {
    int i = blockIdx.x * blockDim.x + threadIdx.x;
    if (i < N_M) g_dinv_m[i] = rsqrtf(g_deg_m[i]);
    else if (i < NTOT) g_dinv_d[i - N_M] = rsqrtf(g_deg_d[i - N_M]);
}

__global__ void k_norm2(const int* __restrict__ e_mm, const int* __restrict__ e_dd) {
    int e = blockIdx.x * blockDim.x + threadIdx.x;
    if (e < E_MM) {
        g_norm_m[e] = g_dinv_m[e_mm[e]] * g_ew_m[e] * g_dinv_m[e_mm[E_MM + e]];
    } else if (e < E_MM + E_DD) {
        int f = e - E_MM;
        g_norm_d[f] = g_dinv_d[e_dd[f]] * g_ew_d[f] * g_dinv_d[e_dd[E_DD + f]];
    }
}

// ---------------- 3 scans in one launch (blockIdx picks the graph) --------
__global__ void k_scan3() {
    __shared__ int sh[1024];
    const int* cnt; int* row; int* cur; int n;
    if (blockIdx.x == 0)      { cnt = g_cnt_m; row = g_row_m; cur = g_cur_m; n = N_M; }
    else if (blockIdx.x == 1) { cnt = g_cnt_d; row = g_row_d; cur = g_cur_d; n = N_D; }
    else                      { cnt = g_cnt_g; row = g_row_g; cur = g_cur_g; n = NTOT; }
    int t = threadIdx.x;
    int chunk = (n + 1023) / 1024;
    int lo = t * chunk, hi = min(lo + chunk, n);
    int sum = 0;
    for (int i = lo; i < hi; i++) sum += cnt[i];
    sh[t] = sum;
    __syncthreads();
    for (int off = 1; off < 1024; off <<= 1) {
        int v = 0;
        if (t >= off) v = sh[t - off];
        __syncthreads();
        if (t >= off) sh[t] += v;
        __syncthreads();
    }
    int run = (t == 0) ? 0 : sh[t - 1];
    for (int i = lo; i < hi; i++) { row[i] = run; cur[i] = run; run += cnt[i]; }
    if (t == 1023) row[n] = sh[1023];
}

// ---------------- combined CSR fill (src + weight stored CSR-ordered) -----
__global__ void k_fill_all(const int* __restrict__ e_mm, const int* __restrict__ e_dd,
                           const int* __restrict__ e_g) {
    int i = blockIdx.x * blockDim.x + threadIdx.x;
    if (i < E_MM) {
        int d = e_mm[E_MM + i];
        int p = atomicAdd(&g_cur_m[d], 1);
        g_src_m[p] = e_mm[i];
        g_w_m[p] = g_norm_m[i];
    } else if (i < E_MM + E_DD) {
        int f = i - E_MM;
        int d = e_dd[E_DD + f];
        int p = atomicAdd(&g_cur_d[d], 1);
        g_src_d[p] = e_dd[f];
        g_w_d[p] = g_norm_d[f];
    } else if (i < E_MM + E_DD + E_G) {
        int f = i - E_MM - E_DD;
        int d = e_g[E_G + f];
        int p = atomicAdd(&g_cur_g[d], 1);
        g_src_g[p] = e_g[f];
    } else if (i < E_MM + E_DD + E_G + NTOT) {
        int f = i - E_MM - E_DD - E_G;     // self loop
        int p = atomicAdd(&g_cur_g[f], 1);
        g_src_g[p] = f;
    }
}

// ---------------- f32 GEMM: 128x128x32 tiles, 8x8/thread, FFMA2 inner -----
// Inner product uses packed fma.rn.f32x2 (dual-lane fp32 FMA, sm_100+):
// 32 FMA2 replace 64 FFMA per thread per k. Numerics identical to FFMA.
struct GTask { const float* A; const float* W1; const float* W2; float* C1; float* C2; int M; };

__global__ __launch_bounds__(256) void k_gemm(
        GTask ta, GTask tb,
        int lda, int Nsplit, int ldw, const float* bias, int ldc, int K) {
    __shared__ float As[32][132];   // [k][m], padded
    __shared__ float Ws[32][128];   // [k][n]
    GTask t = (blockIdx.z == 0) ? ta : tb;
    int row0 = blockIdx.y * 128;
    if (row0 >= t.M) return;
    int col0 = blockIdx.x * 128;
    const float* Wb; float* Cb;
    if (col0 < Nsplit) { Wb = t.W1 + col0;            Cb = t.C1 + col0; }
    else               { Wb = t.W2 + (col0 - Nsplit); Cb = t.C2 + (col0 - Nsplit); }

    int tid = threadIdx.x;
    int tx = tid & 15, ty = tid >> 4;        // 16x16 thread grid, 8x8 each
    unsigned long long acc2[8][4] = {};      // 8 rows x 4 packed f32x2 col-pairs

    for (int k0 = 0; k0 < K; k0 += 32) {
        #pragma unroll
        for (int i = 0; i < 4; i++) {
            int idx = tid + i * 256;
            int r = idx >> 3, c4 = idx & 7;
            float4 v = ld4(t.A + (size_t)(row0 + r) * lda + k0 + c4 * 4);
            As[c4 * 4 + 0][r] = v.x; As[c4 * 4 + 1][r] = v.y;
            As[c4 * 4 + 2][r] = v.z; As[c4 * 4 + 3][r] = v.w;
        }
        #pragma unroll
        for (int i = 0; i < 4; i++) {
            int idx = tid + i * 256;
            int r = idx >> 5, c4 = idx & 31;
            *(float4*)&Ws[r][c4 * 4] = ld4(Wb + (size_t)(k0 + r) * ldw + c4 * 4);
        }
        __syncthreads();
        #pragma unroll 16
        for (int k = 0; k < 32; k++) {
            float a[8];
            *(float4*)&a[0] = *(float4*)&As[k][ty * 8];
            *(float4*)&a[4] = *(float4*)&As[k][ty * 8 + 4];
            unsigned long long bp[4];        // b pairs come straight from LDS.128
            *(float4*)&bp[0] = *(float4*)&Ws[k][tx * 8];
            *(float4*)&bp[2] = *(float4*)&Ws[k][tx * 8 + 4];
            #pragma unroll
            for (int i = 0; i < 8; i++) {
                unsigned long long ap;
                asm("mov.b64 %0, {%1, %1};" : "=l"(ap) : "f"(a[i]));
                #pragma unroll
                for (int j = 0; j < 4; j++)
                    asm("fma.rn.f32x2 %0, %1, %2, %0;"
                        : "+l"(acc2[i][j]) : "l"(ap), "l"(bp[j]));
            }
        }
        __syncthreads();
    }

    float bv[8] = {};
    if (bias) {
        *(float4*)&bv[0] = ld4(bias + col0 + tx * 8);
        *(float4*)&bv[4] = ld4(bias + col0 + tx * 8 + 4);
    }
    #pragma unroll
    for (int i = 0; i < 8; i++) {
        float o[8];
        #pragma unroll
        for (int j = 0; j < 4; j++) {
            float lo, hi;
            asm("mov.b64 {%0, %1}, %2;" : "=f"(lo), "=f"(hi) : "l"(acc2[i][j]));
            o[2 * j]     = lo + bv[2 * j];
            o[2 * j + 1] = hi + bv[2 * j + 1];
        }
        float* pc = Cb + (size_t)(row0 + ty * 8 + i) * ldc + tx * 8;
        *(float4*)pc       = make_float4(o[0], o[1], o[2], o[3]);
        *(float4*)(pc + 4) = make_float4(o[4], o[5], o[6], o[7]);
    }
}

// ---------------- GCN aggregate, both graphs in one launch ----------------
__global__ void k_gcn_agg2(const float* __restrict__ h,
                           const float* __restrict__ bias_m, const float* __restrict__ bias_d,
                           float* __restrict__ out_m, float* __restrict__ out_d,
                           int ldm, int ldd) {
    int w = (blockIdx.x * blockDim.x + threadIdx.x) >> 5;
    int lane = threadIdx.x & 31;
    if (w >= NTOT) return;
    const int* row; const int* src; const float* wcs; const float* bias;
    const float* hb; const float* dinv; float* po; int node;
    if (w < N_M) {
        node = w; row = g_row_m; src = g_src_m; wcs = g_w_m; bias = bias_m;
        hb = h; dinv = g_dinv_m;
        po = out_m + (size_t)w * ldm + lane * 4;
    } else {
        node = w - N_M; row = g_row_d; src = g_src_d; wcs = g_w_d; bias = bias_d;
        hb = h + (size_t)N_M * HID; dinv = g_dinv_d;
        po = out_d + (size_t)(w - N_M) * ldd + lane * 4;
    }
    int rs = row[node], re = row[node + 1];
    float4 acc = make_float4(0.f, 0.f, 0.f, 0.f);
    for (int j = rs; j < re; j++) {
        int s = src[j];
        float nm = wcs[j];
        float4 v = ld4(hb + (size_t)s * HID + lane * 4);
        acc.x += nm * v.x; acc.y += nm * v.y; acc.z += nm * v.z; acc.w += nm * v.w;
    }
    float di = dinv[node];
    float sw = di * di;
    float4 v = ld4(hb + (size_t)node * HID + lane * 4);
    acc.x += sw * v.x; acc.y += sw * v.y; acc.z += sw * v.z; acc.w += sw * v.w;
    float4 b = ld4(bias + lane * 4);
    acc.x = fmaxf(acc.x + b.x, 0.f); acc.y = fmaxf(acc.y + b.y, 0.f);
    acc.z = fmaxf(acc.z + b.z, 0.f); acc.w = fmaxf(acc.w + b.w, 0.f);
    *(float4*)po = acc;
}

// ---------------- Fused GATv2 (warp per dst node, online softmax) ---------
template <int HC>
__global__ void k_gat_fused(const float* __restrict__ xl, const float* __restrict__ xr,
                            const float* __restrict__ att,
                            const float* __restrict__ bias,
                            float* __restrict__ out, int ldout, int elu) {
    const int CH = HC / 32;
    int i = (blockIdx.x * blockDim.x + threadIdx.x) >> 5;
    int lane = threadIdx.x & 31;
    if (i >= NTOT) return;
    int rs = g_row_g[i], re = g_row_g[i + 1];

    float attv[CH], xrv[CH];
    #pragma unroll
    for (int k = 0; k < CH; k += 4) {
        float4 a = ld4(att + lane * CH + k);
        attv[k] = a.x; attv[k + 1] = a.y; attv[k + 2] = a.z; attv[k + 3] = a.w;
        float4 r = ld4(xr + (size_t)i * HC + lane * CH + k);
        xrv[k] = r.x; xrv[k + 1] = r.y; xrv[k + 2] = r.z; xrv[k + 3] = r.w;
    }

    float m = -1e30f, den = 0.f;
    float num[CH];
    #pragma unroll
    for (int k = 0; k < CH; k++) num[k] = 0.f;

    for (int j = rs; j < re; j++) {
        int s = g_src_g[j];
        float xlv[CH];
        float p = 0.f;
        #pragma unroll
        for (int k = 0; k < CH; k += 4) {
            float4 v = ld4(xl + (size_t)s * HC + lane * CH + k);
            xlv[k] = v.x; xlv[k + 1] = v.y; xlv[k + 2] = v.z; xlv[k + 3] = v.w;
        }
        #pragma unroll
        for (int k = 0; k < CH; k++) {
            float t = xlv[k] + xrv[k];
            t = t > 0.f ? t : 0.2f * t;
            p += t * attv[k];
        }
        p += __shfl_xor_sync(0xffffffffu, p, 1);
        p += __shfl_xor_sync(0xffffffffu, p, 2);
        p += __shfl_xor_sync(0xffffffffu, p, 4);
        float mn = fmaxf(m, p);
        float c  = expf(m - mn);      // first iter: exp(-huge) = 0
        float ex = expf(p - mn);
        den = den * c + ex;
        #pragma unroll
        for (int k = 0; k < CH; k++) num[k] = num[k] * c + ex * xlv[k];
        m = mn;
    }

    float inv = 0.25f / den;   // includes 1/H head-mean
    #pragma unroll
    for (int k = 0; k < CH; k++) {
        float v = num[k] * inv;
        v += __shfl_xor_sync(0xffffffffu, v, 8);
        v += __shfl_xor_sync(0xffffffffu, v, 16);
        num[k] = v;
    }
    if (lane < 8) {
        float o[CH];
        #pragma unroll
        for (int k = 0; k < CH; k++) {
            float v = num[k] + bias[lane * CH + k];
            if (elu) v = v > 0.f ? v : expm1f(v);
            o[k] = v;
        }
        float* po = out + (size_t)i * ldout + lane * CH;
        #pragma unroll
        for (int k = 0; k < CH; k += 4)
            *(float4*)(po + k) = make_float4(o[k], o[k + 1], o[k + 2], o[k + 3]);
    }
}

// ---------------- host orchestration ----------------
extern "C" void kernel_launch(void* const* d_in, const int* in_sizes, int n_in,
                              void* d_out, int out_size) {
    const float* mm_f = (const float*)d_in[0];
    const float* d_s  = (const float*)d_in[1];
    const float* msM  = (const float*)d_in[2];
    const float* dsM  = (const float*)d_in[3];
    const int*   e_mm = (const int*)d_in[4];
    const int*   e_dd = (const int*)d_in[5];
    const int*   e_g  = (const int*)d_in[6];
    const float* W_m1 = (const float*)d_in[7];  const float* b_m1 = (const float*)d_in[8];
    const float* W_m2 = (const float*)d_in[9];  const float* b_m2 = (const float*)d_in[10];
    const float* W_d1 = (const float*)d_in[11]; const float* b_d1 = (const float*)d_in[12];
    const float* W_d2 = (const float*)d_in[13]; const float* b_d2 = (const float*)d_in[14];
    const float* Wl1  = (const float*)d_in[15]; const float* Wr1  = (const float*)d_in[16];
    const float* att1 = (const float*)d_in[17]; const float* bias1 = (const float*)d_in[18];
    const float* Wl2  = (const float*)d_in[19]; const float* Wr2  = (const float*)d_in[20];
    const float* att2 = (const float*)d_in[21]; const float* bias2 = (const float*)d_in[22];
    const float* Wjk  = (const float*)d_in[23]; const float* bjk  = (const float*)d_in[24];
    float* out = (float*)d_out;

    float *p_A, *p_B, *p_tmp, *p_xjk;
    cudaGetSymbolAddress((void**)&p_A,   g_bufA);
    cudaGetSymbolAddress((void**)&p_B,   g_bufB);
    cudaGetSymbolAddress((void**)&p_tmp, g_tmp);
    cudaGetSymbolAddress((void**)&p_xjk, g_xjk);

    const int GB = TPB;
    auto blk = [](int n) { return (n + TPB - 1) / TPB; };
    auto wblk = [](int nwarps) { return (nwarps * 32 + TPB - 1) / TPB; };

    // ---- prep: 6 launches ----
    k_init<<<blk(NTOT), GB>>>();
    k_prep_all<<<blk(E_MM + E_DD + E_G), GB>>>(e_mm, msM, e_dd, dsM, e_g);
    k_dinv2<<<blk(NTOT), GB>>>();
    k_norm2<<<blk(E_MM + E_DD), GB>>>(e_mm, e_dd);
    k_scan3<<<3, 1024>>>();
    k_fill_all<<<blk(E_MM + E_DD + E_G + NTOT), GB>>>(e_mm, e_dd, e_g);

    // ---- GCN layer 1 (m + d fused via blockIdx.z) ----
    {
        GTask ta = { mm_f, W_m1, W_m1, p_A,                      p_A,                      N_M };
        GTask tb = { d_s,  W_d1, W_d1, p_A + (size_t)N_M * HID,  p_A + (size_t)N_M * HID,  N_D };
        k_gemm<<<dim3(1, N_M / 128, 2), 256>>>(ta, tb, HID, 128, HID, nullptr, HID, HID);
    }
    k_gcn_agg2<<<wblk(NTOT), GB>>>(p_A, b_m1, b_d1, p_tmp, p_tmp + (size_t)N_M * HID, HID, HID);

    // ---- GCN layer 2 ----
    {
        GTask ta = { p_tmp,                      W_m2, W_m2, p_A,                     p_A,                     N_M };
        GTask tb = { p_tmp + (size_t)N_M * HID,  W_d2, W_d2, p_A + (size_t)N_M * HID, p_A + (size_t)N_M * HID, N_D };
        k_gemm<<<dim3(1, N_M / 128, 2), 256>>>(ta, tb, HID, 128, HID, nullptr, HID, HID);
    }
    // x0 = relu(gcn2) into xjk cols [0,128)
    k_gcn_agg2<<<wblk(NTOT), GB>>>(p_A, b_m2, b_d2, p_xjk, p_xjk + (size_t)N_M * 224, 224, 224);

    // ---- GATv2 layer 1: xl|xr in ONE dual-W GEMM (K=128, Nc=256+256) ----
    {
        GTask ta = { p_xjk, Wl1, Wr1, p_A, p_B, NTOT };
        k_gemm<<<dim3(4, NTOT / 128, 1), 256>>>(ta, ta, 224, 256, 256, nullptr, 256, 128);
    }
    k_gat_fused<256><<<wblk(NTOT), GB>>>(p_A, p_B, att1, bias1, p_xjk + 128, 224, 1);

    // ---- GATv2 layer 2 (K=64, Nc=128+128) ----
    {
        GTask ta = { p_xjk + 128, Wl2, Wr2, p_A, p_B, NTOT };
        k_gemm<<<dim3(2, NTOT / 128, 1), 256>>>(ta, ta, 224, 128, 128, nullptr, 128, 64);
    }
    k_gat_fused<128><<<wblk(NTOT), GB>>>(p_A, p_B, att2, bias2, p_xjk + 192, 224, 0);

    // ---- JumpingKnowledge linear: out = [x0|x1|x2] @ Wjk + bjk ----
    {
        GTask ta = { p_xjk, Wjk, Wjk, out, out, NTOT };
        k_gemm<<<dim3(1, NTOT / 128, 1), 256>>>(ta, ta, 224, 128, 128, bjk, 128, 224);
    }
}

// round 7
// speedup vs baseline: 1.6826x; 1.0809x over previous
#include <cuda_runtime.h>
#include <math.h>
#include <stdint.h>

// ---------------- problem constants (fixed by the dataset) ----------------
#define N_M   8192
#define N_D   6144
#define NTOT  14336            // N_M + N_D
#define E_MM  131072
#define E_DD  98304
#define E_G   229376
#define EG_TOT (E_G + NTOT)    // real edges + self loops = 243712
#define HID   128
#define TPB   256

// ---------------- scratch (static device globals; no runtime alloc) -------
__device__ float g_ew_m[E_MM];
__device__ float g_ew_d[E_DD];
__device__ float g_deg_m[N_M];
__device__ float g_deg_d[N_D];
__device__ int   g_cnt_m[N_M],  g_row_m[N_M + 1],  g_cur_m[N_M];
__device__ int   g_src_m[E_MM];  __device__ float g_w_m[E_MM];
__device__ int   g_cnt_d[N_D],  g_row_d[N_D + 1],  g_cur_d[N_D];
__device__ int   g_src_d[E_DD];  __device__ float g_w_d[E_DD];
__device__ int   g_cnt_g[NTOT], g_row_g[NTOT + 1], g_cur_g[NTOT];
__device__ int   g_src_g[EG_TOT];
__device__ float g_bufA[(size_t)NTOT * 256];
__device__ float g_bufB[(size_t)NTOT * 256];
__device__ float g_tmp [(size_t)NTOT * 128];
__device__ float g_xjk [(size_t)NTOT * 224];

__device__ __forceinline__ float4 ld4(const float* p) { return *(const float4*)p; }

// tf32 conversion (round-to-nearest) — bit pattern in a u32
__device__ __forceinline__ uint32_t f2tf(float x) {
    uint32_t r;
    asm("cvt.rna.tf32.f32 %0, %1;" : "=r"(r) : "f"(x));
    return r;
}

// one m16n8k8 tf32 mma, D += A*B (D==C in-place)
__device__ __forceinline__ void mma8(float* d, const uint32_t* a, uint32_t b0, uint32_t b1) {
    asm("mma.sync.aligned.m16n8k8.row.col.f32.tf32.tf32.f32 "
        "{%0,%1,%2,%3}, {%4,%5,%6,%7}, {%8,%9}, {%0,%1,%2,%3};"
        : "+f"(d[0]), "+f"(d[1]), "+f"(d[2]), "+f"(d[3])
        : "r"(a[0]), "r"(a[1]), "r"(a[2]), "r"(a[3]), "r"(b0), "r"(b1));
}

// ---------------- init ----------------
__global__ void k_init() {
    int i = blockIdx.x * blockDim.x + threadIdx.x;
    if (i < N_M)  { g_deg_m[i] = 1.0f; g_cnt_m[i] = 0; }   // self-loop weight 1
    if (i < N_D)  { g_deg_d[i] = 1.0f; g_cnt_d[i] = 0; }
    if (i < NTOT) { g_cnt_g[i] = 1; }                       // self loop pre-counted
}

// ---------------- combined edge prep (both GCN graphs + GAT count) --------
__global__ void k_prep_all(const int* __restrict__ e_mm, const float* __restrict__ msM,
                           const int* __restrict__ e_dd, const float* __restrict__ dsM,
                           const int* __restrict__ e_g) {
    int i = blockIdx.x * blockDim.x + threadIdx.x;
    if (i < E_MM) {
        int s = e_mm[i], d = e_mm[E_MM + i];
        float w = msM[(size_t)s * N_M + d];
        g_ew_m[i] = w;
        atomicAdd(&g_deg_m[d], w);
        atomicAdd(&g_cnt_m[d], 1);
    } else if (i < E_MM + E_DD) {
        int f = i - E_MM;
        int s = e_dd[f], d = e_dd[E_DD + f];
        float w = dsM[(size_t)s * N_D + d];
        g_ew_d[f] = w;
        atomicAdd(&g_deg_d[d], w);
        atomicAdd(&g_cnt_d[d], 1);
    } else if (i < E_MM + E_DD + E_G) {
        int f = i - E_MM - E_DD;
        atomicAdd(&g_cnt_g[e_g[E_G + f]], 1);
    }
}

// ---------------- 3 scans in one launch (blockIdx picks the graph) --------
__global__ void k_scan3() {
    __shared__ int sh[1024];
    const int* cnt; int* row; int* cur; int n;
    if (blockIdx.x == 0)      { cnt = g_cnt_m; row = g_row_m; cur = g_cur_m; n = N_M; }
    else if (blockIdx.x == 1) { cnt = g_cnt_d; row = g_row_d; cur = g_cur_d; n = N_D; }
    else                      { cnt = g_cnt_g; row = g_row_g; cur = g_cur_g; n = NTOT; }
    int t = threadIdx.x;
    int chunk = (n + 1023) / 1024;
    int lo = t * chunk, hi = min(lo + chunk, n);
    int sum = 0;
    for (int i = lo; i < hi; i++) sum += cnt[i];
    sh[t] = sum;
    __syncthreads();
    for (int off = 1; off < 1024; off <<= 1) {
        int v = 0;
        if (t >= off) v = sh[t - off];
        __syncthreads();
        if (t >= off) sh[t] += v;
        __syncthreads();
    }
    int run = (t == 0) ? 0 : sh[t - 1];
    for (int i = lo; i < hi; i++) { row[i] = run; cur[i] = run; run += cnt[i]; }
    if (t == 1023) row[n] = sh[1023];
}

// ---------------- combined CSR fill; GCN norm computed inline -------------
__global__ void k_fill_all(const int* __restrict__ e_mm, const int* __restrict__ e_dd,
                           const int* __restrict__ e_g) {
    int i = blockIdx.x * blockDim.x + threadIdx.x;
    if (i < E_MM) {
        int s = e_mm[i], d = e_mm[E_MM + i];
        int p = atomicAdd(&g_cur_m[d], 1);
        g_src_m[p] = s;
        g_w_m[p] = rsqrtf(g_deg_m[s]) * g_ew_m[i] * rsqrtf(g_deg_m[d]);
    } else if (i < E_MM + E_DD) {
        int f = i - E_MM;
        int s = e_dd[f], d = e_dd[E_DD + f];
        int p = atomicAdd(&g_cur_d[d], 1);
        g_src_d[p] = s;
        g_w_d[p] = rsqrtf(g_deg_d[s]) * g_ew_d[f] * rsqrtf(g_deg_d[d]);
    } else if (i < E_MM + E_DD + E_G) {
        int f = i - E_MM - E_DD;
        int d = e_g[E_G + f];
        int p = atomicAdd(&g_cur_g[d], 1);
        g_src_g[p] = e_g[f];
    } else if (i < E_MM + E_DD + E_G + NTOT) {
        int f = i - E_MM - E_DD - E_G;     // self loop
        int p = atomicAdd(&g_cur_g[f], 1);
        g_src_g[p] = f;
    }
}

// ---------------- tf32x3 tensor-core GEMM: 128x128x16 tiles ----------------
// 8 warps (4x2), warp tile m32 x n64, mma.m16n8k8.tf32, 3-pass compensation:
// D = Ahi*Blo + Alo*Bhi + Ahi*Bhi   (error ~1e-7, near-fp32)
struct GTask { const float* A; const float* W1; const float* W2; float* C1; float* C2; int M; };

__global__ __launch_bounds__(256) void k_gemm(
        GTask ta, GTask tb,
        int lda, int Nsplit, int ldw, const float* bias, int ldc, int K) {
    __shared__ uint32_t As_h[16][132], As_l[16][132];   // [k][m], pad 4
    __shared__ uint32_t Bs_h[16][132], Bs_l[16][132];   // [k][n], pad 4
    GTask t = (blockIdx.z == 0) ? ta : tb;
    int row0 = blockIdx.y * 128;
    if (row0 >= t.M) return;
    int col0 = blockIdx.x * 128;
    const float* Wb; float* Cb;
    if (col0 < Nsplit) { Wb = t.W1 + col0;            Cb = t.C1 + col0; }
    else               { Wb = t.W2 + (col0 - Nsplit); Cb = t.C2 + (col0 - Nsplit); }

    int tid = threadIdx.x;
    int lane = tid & 31, wid = tid >> 5;
    int warp_m = wid & 3, warp_n = wid >> 2;   // 4 x 2 warp grid
    int g = lane >> 2, tg = lane & 3;
    int mbase = warp_m * 32, nbase0 = warp_n * 64;

    float acc[2][8][4];
    #pragma unroll
    for (int mi = 0; mi < 2; mi++)
        #pragma unroll
        for (int ni = 0; ni < 8; ni++)
            #pragma unroll
            for (int q = 0; q < 4; q++) acc[mi][ni][q] = 0.f;

    for (int k0 = 0; k0 < K; k0 += 16) {
        // A tile 128x16 -> As[k][m] (transposed), split hi/lo
        #pragma unroll
        for (int i = 0; i < 2; i++) {
            int idx = tid + i * 256;
            int r = idx >> 2, c4 = idx & 3;
            float4 v = ld4(t.A + (size_t)(row0 + r) * lda + k0 + c4 * 4);
            float e[4] = {v.x, v.y, v.z, v.w};
            #pragma unroll
            for (int j = 0; j < 4; j++) {
                uint32_t h = f2tf(e[j]);
                As_h[c4 * 4 + j][r] = h;
                As_l[c4 * 4 + j][r] = f2tf(e[j] - __uint_as_float(h));
            }
        }
        // B tile 16x128 -> Bs[k][n], split hi/lo (vectorized stores)
        #pragma unroll
        for (int i = 0; i < 2; i++) {
            int idx = tid + i * 256;
            int r = idx >> 5, c4 = idx & 31;
            float4 v = ld4(Wb + (size_t)(k0 + r) * ldw + c4 * 4);
            uint4 hv, lv;
            hv.x = f2tf(v.x); lv.x = f2tf(v.x - __uint_as_float(hv.x));
            hv.y = f2tf(v.y); lv.y = f2tf(v.y - __uint_as_float(hv.y));
            hv.z = f2tf(v.z); lv.z = f2tf(v.z - __uint_as_float(hv.z));
            hv.w = f2tf(v.w); lv.w = f2tf(v.w - __uint_as_float(hv.w));
            *(uint4*)&Bs_h[r][c4 * 4] = hv;
            *(uint4*)&Bs_l[r][c4 * 4] = lv;
        }
        __syncthreads();

        #pragma unroll
        for (int ks = 0; ks < 16; ks += 8) {
            // A fragments (2 m16-tiles, hi+lo)
            uint32_t ah[2][4], al[2][4];
            #pragma unroll
            for (int mi = 0; mi < 2; mi++) {
                int m0 = mbase + mi * 16;
                ah[mi][0] = As_h[ks + tg][m0 + g];
                ah[mi][1] = As_h[ks + tg][m0 + g + 8];
                ah[mi][2] = As_h[ks + tg + 4][m0 + g];
                ah[mi][3] = As_h[ks + tg + 4][m0 + g + 8];
                al[mi][0] = As_l[ks + tg][m0 + g];
                al[mi][1] = As_l[ks + tg][m0 + g + 8];
                al[mi][2] = As_l[ks + tg + 4][m0 + g];
                al[mi][3] = As_l[ks + tg + 4][m0 + g + 8];
            }
            #pragma unroll
            for (int ni = 0; ni < 8; ni++) {
                int n0 = nbase0 + ni * 8;
                uint32_t bh0 = Bs_h[ks + tg][n0 + g];
                uint32_t bh1 = Bs_h[ks + tg + 4][n0 + g];
                uint32_t bl0 = Bs_l[ks + tg][n0 + g];
                uint32_t bl1 = Bs_l[ks + tg + 4][n0 + g];
                #pragma unroll
                for (int mi = 0; mi < 2; mi++) {
                    mma8(acc[mi][ni], ah[mi], bl0, bl1);   // hi * lo
                    mma8(acc[mi][ni], al[mi], bh0, bh1);   // lo * hi
                    mma8(acc[mi][ni], ah[mi], bh0, bh1);   // hi * hi
                }
            }
        }
        __syncthreads();
    }

    // epilogue: thread owns rows {g, g+8} of each m16 tile, cols {2tg, 2tg+1}
    #pragma unroll
    for (int mi = 0; mi < 2; mi++) {
        int r0 = row0 + mbase + mi * 16 + g;
        #pragma unroll
        for (int ni = 0; ni < 8; ni++) {
            int lc = nbase0 + ni * 8 + tg * 2;
            float b0 = 0.f, b1 = 0.f;
            if (bias) { b0 = bias[col0 + lc]; b1 = bias[col0 + lc + 1]; }
            float* p0 = Cb + (size_t)r0 * ldc + lc;
            float* p1 = p0 + (size_t)8 * ldc;
            *(float2*)p0 = make_float2(acc[mi][ni][0] + b0, acc[mi][ni][1] + b1);
            *(float2*)p1 = make_float2(acc[mi][ni][2] + b0, acc[mi][ni][3] + b1);
        }
    }
}

// ---------------- GCN aggregate, both graphs in one launch ----------------
__global__ void k_gcn_agg2(const float* __restrict__ h,
                           const float* __restrict__ bias_m, const float* __restrict__ bias_d,
                           float* __restrict__ out_m, float* __restrict__ out_d,
                           int ldm, int ldd) {
    int w = (blockIdx.x * blockDim.x + threadIdx.x) >> 5;
    int lane = threadIdx.x & 31;
    if (w >= NTOT) return;
    const int* row; const int* src; const float* wcs; const float* bias;
    const float* hb; const float* deg; float* po; int node;
    if (w < N_M) {
        node = w; row = g_row_m; src = g_src_m; wcs = g_w_m; bias = bias_m;
        hb = h; deg = g_deg_m;
        po = out_m + (size_t)w * ldm + lane * 4;
    } else {
        node = w - N_M; row = g_row_d; src = g_src_d; wcs = g_w_d; bias = bias_d;
        hb = h + (size_t)N_M * HID; deg = g_deg_d;
        po = out_d + (size_t)(w - N_M) * ldd + lane * 4;
    }
    int rs = row[node], re = row[node + 1];
    float4 acc = make_float4(0.f, 0.f, 0.f, 0.f);
    for (int j = rs; j < re; j++) {
        int s = src[j];
        float nm = wcs[j];
        float4 v = ld4(hb + (size_t)s * HID + lane * 4);
        acc.x += nm * v.x; acc.y += nm * v.y; acc.z += nm * v.z; acc.w += nm * v.w;
    }
    float di = rsqrtf(deg[node]);
    float sw = di * di;
    float4 v = ld4(hb + (size_t)node * HID + lane * 4);
    acc.x += sw * v.x; acc.y += sw * v.y; acc.z += sw * v.z; acc.w += sw * v.w;
    float4 b = ld4(bias + lane * 4);
    acc.x = fmaxf(acc.x + b.x, 0.f); acc.y = fmaxf(acc.y + b.y, 0.f);
    acc.z = fmaxf(acc.z + b.z, 0.f); acc.w = fmaxf(acc.w + b.w, 0.f);
    *(float4*)po = acc;
}

// ---------------- Fused GATv2 (warp per dst node, online softmax) ---------
template <int HC>
__global__ void k_gat_fused(const float* __restrict__ xl, const float* __restrict__ xr,
                            const float* __restrict__ att,
                            const float* __restrict__ bias,
                            float* __restrict__ out, int ldout, int elu) {
    const int CH = HC / 32;
    int i = (blockIdx.x * blockDim.x + threadIdx.x) >> 5;
    int lane = threadIdx.x & 31;
    if (i >= NTOT) return;
    int rs = g_row_g[i], re = g_row_g[i + 1];

    float attv[CH], xrv[CH];
    #pragma unroll
    for (int k = 0; k < CH; k += 4) {
        float4 a = ld4(att + lane * CH + k);
        attv[k] = a.x; attv[k + 1] = a.y; attv[k + 2] = a.z; attv[k + 3] = a.w;
        float4 r = ld4(xr + (size_t)i * HC + lane * CH + k);
        xrv[k] = r.x; xrv[k + 1] = r.y; xrv[k + 2] = r.z; xrv[k + 3] = r.w;
    }

    float m = -1e30f, den = 0.f;
    float num[CH];
    #pragma unroll
    for (int k = 0; k < CH; k++) num[k] = 0.f;

    for (int j = rs; j < re; j++) {
        int s = g_src_g[j];
        float xlv[CH];
        float p = 0.f;
        #pragma unroll
        for (int k = 0; k < CH; k += 4) {
            float4 v = ld4(xl + (size_t)s * HC + lane * CH + k);
            xlv[k] = v.x; xlv[k + 1] = v.y; xlv[k + 2] = v.z; xlv[k + 3] = v.w;
        }
        #pragma unroll
        for (int k = 0; k < CH; k++) {
            float t = xlv[k] + xrv[k];
            t = t > 0.f ? t : 0.2f * t;
            p += t * attv[k];
        }
        p += __shfl_xor_sync(0xffffffffu, p, 1);
        p += __shfl_xor_sync(0xffffffffu, p, 2);
        p += __shfl_xor_sync(0xffffffffu, p, 4);
        float mn = fmaxf(m, p);
        float c  = expf(m - mn);      // first iter: exp(-huge) = 0
        float ex = expf(p - mn);
        den = den * c + ex;
        #pragma unroll
        for (int k = 0; k < CH; k++) num[k] = num[k] * c + ex * xlv[k];
        m = mn;
    }

    float inv = 0.25f / den;   // includes 1/H head-mean
    #pragma unroll
    for (int k = 0; k < CH; k++) {
        float v = num[k] * inv;
        v += __shfl_xor_sync(0xffffffffu, v, 8);
        v += __shfl_xor_sync(0xffffffffu, v, 16);
        num[k] = v;
    }
    if (lane < 8) {
        float o[CH];
        #pragma unroll
        for (int k = 0; k < CH; k++) {
            float v = num[k] + bias[lane * CH + k];
            if (elu) v = v > 0.f ? v : expm1f(v);
            o[k] = v;
        }
        float* po = out + (size_t)i * ldout + lane * CH;
        #pragma unroll
        for (int k = 0; k < CH; k += 4)
            *(float4*)(po + k) = make_float4(o[k], o[k + 1], o[k + 2], o[k + 3]);
    }
}

// ---------------- host orchestration ----------------
extern "C" void kernel_launch(void* const* d_in, const int* in_sizes, int n_in,
                              void* d_out, int out_size) {
    const float* mm_f = (const float*)d_in[0];
    const float* d_s  = (const float*)d_in[1];
    const float* msM  = (const float*)d_in[2];
    const float* dsM  = (const float*)d_in[3];
    const int*   e_mm = (const int*)d_in[4];
    const int*   e_dd = (const int*)d_in[5];
    const int*   e_g  = (const int*)d_in[6];
    const float* W_m1 = (const float*)d_in[7];  const float* b_m1 = (const float*)d_in[8];
    const float* W_m2 = (const float*)d_in[9];  const float* b_m2 = (const float*)d_in[10];
    const float* W_d1 = (const float*)d_in[11]; const float* b_d1 = (const float*)d_in[12];
    const float* W_d2 = (const float*)d_in[13]; const float* b_d2 = (const float*)d_in[14];
    const float* Wl1  = (const float*)d_in[15]; const float* Wr1  = (const float*)d_in[16];
    const float* att1 = (const float*)d_in[17]; const float* bias1 = (const float*)d_in[18];
    const float* Wl2  = (const float*)d_in[19]; const float* Wr2  = (const float*)d_in[20];
    const float* att2 = (const float*)d_in[21]; const float* bias2 = (const float*)d_in[22];
    const float* Wjk  = (const float*)d_in[23]; const float* bjk  = (const float*)d_in[24];
    float* out = (float*)d_out;

    float *p_A, *p_B, *p_tmp, *p_xjk;
    cudaGetSymbolAddress((void**)&p_A,   g_bufA);
    cudaGetSymbolAddress((void**)&p_B,   g_bufB);
    cudaGetSymbolAddress((void**)&p_tmp, g_tmp);
    cudaGetSymbolAddress((void**)&p_xjk, g_xjk);

    const int GB = TPB;
    auto blk = [](int n) { return (n + TPB - 1) / TPB; };
    auto wblk = [](int nwarps) { return (nwarps * 32 + TPB - 1) / TPB; };

    // ---- prep: 4 launches ----
    k_init<<<blk(NTOT), GB>>>();
    k_prep_all<<<blk(E_MM + E_DD + E_G), GB>>>(e_mm, msM, e_dd, dsM, e_g);
    k_scan3<<<3, 1024>>>();
    k_fill_all<<<blk(E_MM + E_DD + E_G + NTOT), GB>>>(e_mm, e_dd, e_g);

    // ---- GCN layer 1 (m + d fused via blockIdx.z) ----
    {
        GTask ta = { mm_f, W_m1, W_m1, p_A,                      p_A,                      N_M };
        GTask tb = { d_s,  W_d1, W_d1, p_A + (size_t)N_M * HID,  p_A + (size_t)N_M * HID,  N_D };
        k_gemm<<<dim3(1, N_M / 128, 2), 256>>>(ta, tb, HID, 128, HID, nullptr, HID, HID);
    }
    k_gcn_agg2<<<wblk(NTOT), GB>>>(p_A, b_m1, b_d1, p_tmp, p_tmp + (size_t)N_M * HID, HID, HID);

    // ---- GCN layer 2 ----
    {
        GTask ta = { p_tmp,                      W_m2, W_m2, p_A,                     p_A,                     N_M };
        GTask tb = { p_tmp + (size_t)N_M * HID,  W_d2, W_d2, p_A + (size_t)N_M * HID, p_A + (size_t)N_M * HID, N_D };
        k_gemm<<<dim3(1, N_M / 128, 2), 256>>>(ta, tb, HID, 128, HID, nullptr, HID, HID);
    }
    // x0 = relu(gcn2) into xjk cols [0,128)
    k_gcn_agg2<<<wblk(NTOT), GB>>>(p_A, b_m2, b_d2, p_xjk, p_xjk + (size_t)N_M * 224, 224, 224);

    // ---- GATv2 layer 1: xl|xr in ONE dual-W GEMM (K=128, Nc=256+256) ----
    {
        GTask ta = { p_xjk, Wl1, Wr1, p_A, p_B, NTOT };
        k_gemm<<<dim3(4, NTOT / 128, 1), 256>>>(ta, ta, 224, 256, 256, nullptr, 256, 128);
    }
    k_gat_fused<256><<<wblk(NTOT), GB>>>(p_A, p_B, att1, bias1, p_xjk + 128, 224, 1);

    // ---- GATv2 layer 2 (K=64, Nc=128+128) ----
    {
        GTask ta = { p_xjk + 128, Wl2, Wr2, p_A, p_B, NTOT };
        k_gemm<<<dim3(2, NTOT / 128, 1), 256>>>(ta, ta, 224, 128, 128, nullptr, 128, 64);
    }
    k_gat_fused<128><<<wblk(NTOT), GB>>>(p_A, p_B, att2, bias2, p_xjk + 192, 224, 0);

    // ---- JumpingKnowledge linear: out = [x0|x1|x2] @ Wjk + bjk ----
    {
        GTask ta = { p_xjk, Wjk, Wjk, out, out, NTOT };
        k_gemm<<<dim3(1, NTOT / 128, 1), 256>>>(ta, ta, 224, 128, 128, bjk, 128, 224);
    }
}